// round 1
// baseline (speedup 1.0000x reference)
#include <cuda_runtime.h>
#include <math.h>

#define N_TOK   8192
#define IN_LEN  512
#define OUT_LEN 512
#define NE      8
#define NI      16
#define NPAIR   (N_TOK*2)
#define MAX_TILES (NPAIR/128 + NE)   // 136

// ---------------- device scratch (no runtime allocation allowed) ----------------
__device__ float g_mean_ins[OUT_LEN];
__device__ float g_rgamma[NE];
__device__ float g_gam[NE];
__device__ float g_bet[NE*OUT_LEN];
__device__ int   g_sel[NPAIR];
__device__ float g_rw[NPAIR];
__device__ int   g_count[NE];
__device__ int   g_off[NE];
__device__ int   g_cursor[NE];
__device__ int   g_tile_start[NE+1];
__device__ int   g_list[NPAIR];
__device__ float g_lcoef[NPAIR];
__device__ int   g_tslot[NPAIR];
__device__ float g_stage[(size_t)NPAIR*OUT_LEN];   // 33.5 MB staging

// ---------------- K1: mean_ins, router_gamma, gam; zero counts ----------------
__global__ void k_prep(const float* __restrict__ ins,
                       const float* __restrict__ rmod,
                       const float* __restrict__ gammaw) {
    int h = threadIdx.x;               // 512 threads
    float s = 0.f;
#pragma unroll
    for (int n = 0; n < NI; n++) s += ins[n*OUT_LEN + h];
    s *= (1.f/NI);
    g_mean_ins[h] = s;
    __shared__ float sm[OUT_LEN];
    sm[h] = s;
    if (h < NE) g_count[h] = 0;
    __syncthreads();
    if (h < NE) {
        float a = 0.f, b = 0.f;
        for (int k = 0; k < OUT_LEN; k++) {
            float m = sm[k];
            a += m * rmod[k*NE + h];          // rmod_w: [out_len, E]
            b += m * gammaw[h*OUT_LEN + k];   // gamma_w: [E, out_len]
        }
        g_rgamma[h] = a;
        g_gam[h]    = b;
    }
}

// ---------------- K2: bet_eff[e,d] = mean_ins @ beta_w[e] + gam[e]*expert_b[e] ----------------
__global__ void k_beta(const float* __restrict__ betaw,
                       const float* __restrict__ eb) {
    int e = blockIdx.x;
    int d = blockIdx.y*128 + threadIdx.x;
    const float* bw = betaw + (size_t)e*OUT_LEN*OUT_LEN + d;
    float s = 0.f;
#pragma unroll 8
    for (int h = 0; h < OUT_LEN; h++) s += g_mean_ins[h] * bw[(size_t)h*OUT_LEN];
    g_bet[e*OUT_LEN + d] = s + g_gam[e] * eb[e*OUT_LEN + d];
}

// ---------------- K3: routing (one warp per token) ----------------
__global__ void k_route(const float* __restrict__ x,
                        const float* __restrict__ gatew) {
    int warp = threadIdx.x >> 5;
    int lane = threadIdx.x & 31;
    int t = blockIdx.x*8 + warp;
    const float* xr = x + (size_t)t*IN_LEN;
    float acc[NE];
#pragma unroll
    for (int e = 0; e < NE; e++) acc[e] = 0.f;
    for (int i = 0; i < IN_LEN/32; i++) {
        float xv = xr[i*32 + lane];
        const float* gw = gatew + (size_t)(i*32 + lane)*NE;   // gate_w: [in_len, E]
#pragma unroll
        for (int e = 0; e < NE; e++) acc[e] = fmaf(xv, gw[e], acc[e]);
    }
#pragma unroll
    for (int e = 0; e < NE; e++)
#pragma unroll
        for (int o = 16; o > 0; o >>= 1)
            acc[e] += __shfl_xor_sync(0xffffffffu, acc[e], o);
    if (lane == 0) {
        float l[NE];
#pragma unroll
        for (int e = 0; e < NE; e++) l[e] = acc[e] + g_rgamma[e];
        float m = l[0];
#pragma unroll
        for (int e = 1; e < NE; e++) m = fmaxf(m, l[e]);
        float s = 0.f;
#pragma unroll
        for (int e = 0; e < NE; e++) s += expf(l[e] - m);
        float inv = 1.f / s;
        // top-2, strict > keeps lowest index on ties (matches jax.lax.top_k)
        int e0 = 0; float v0 = l[0];
#pragma unroll
        for (int e = 1; e < NE; e++) if (l[e] > v0) { v0 = l[e]; e0 = e; }
        int e1 = -1; float v1 = -INFINITY;
#pragma unroll
        for (int e = 0; e < NE; e++) if (e != e0 && l[e] > v1) { v1 = l[e]; e1 = e; }
        g_sel[2*t]   = e0;  g_sel[2*t+1] = e1;
        g_rw[2*t]    = expf(v0 - m) * inv;
        g_rw[2*t+1]  = expf(v1 - m) * inv;
        atomicAdd(&g_count[e0], 1);
        atomicAdd(&g_count[e1], 1);
    }
}

// ---------------- K4: prefix sums, tile starts, zero cursors ----------------
__global__ void k_offsets() {
    if (threadIdx.x == 0 && blockIdx.x == 0) {
        int off = 0, ts = 0;
        for (int e = 0; e < NE; e++) {
            g_off[e] = off;
            g_tile_start[e] = ts;
            g_cursor[e] = 0;
            off += g_count[e];
            ts  += (g_count[e] + 127) >> 7;
        }
        g_tile_start[NE] = ts;
    }
}

// ---------------- K5: scatter tokens into per-expert lists ----------------
__global__ void k_scatter() {
    int t = blockIdx.x*blockDim.x + threadIdx.x;
    if (t >= N_TOK) return;
#pragma unroll
    for (int k = 0; k < 2; k++) {
        int e = g_sel[2*t + k];
        float rw = g_rw[2*t + k];
        int slot = g_off[e] + atomicAdd(&g_cursor[e], 1);
        g_list[slot]  = t;
        g_lcoef[slot] = rw * g_gam[e];
        g_tslot[2*t + k] = slot;
    }
}

// ---------------- K6: grouped GEMM, 128x64 tile, 8x4 microtile, fp32 ----------------
__global__ __launch_bounds__(256) void k_gemm(const float* __restrict__ x,
                                              const float* __restrict__ ew) {
    int rt = blockIdx.x;
    int total = g_tile_start[NE];
    if (rt >= total) return;
    int e = 0;
#pragma unroll
    for (int i = 1; i < NE; i++) if (g_tile_start[i] <= rt) e = i;
    int tile_in_e = rt - g_tile_start[e];
    int rbase = g_off[e] + tile_in_e*128;
    int nrows = g_count[e] - tile_in_e*128;
    if (nrows > 128) nrows = 128;
    int cbase = blockIdx.y*64;

    __shared__ float Xs[32][132];   // [k][row], padded: conflict-free f4 reads
    __shared__ float Ws[32][68];    // [k][col]
    __shared__ int   s_tok[128];
    __shared__ float s_coef[128];

    int tid = threadIdx.x;
    if (tid < 128) {
        if (tid < nrows) { s_tok[tid] = g_list[rbase + tid]; s_coef[tid] = g_lcoef[rbase + tid]; }
        else             { s_tok[tid] = g_list[rbase];       s_coef[tid] = 0.f; }
    }
    __syncthreads();

    int ty = tid >> 4, tx = tid & 15;   // rows ty*8..+7, cols tx*4..+3
    float acc[8][4];
#pragma unroll
    for (int i = 0; i < 8; i++)
#pragma unroll
        for (int j = 0; j < 4; j++) acc[i][j] = 0.f;

    const float* wb0 = ew + (size_t)e*IN_LEN*OUT_LEN + cbase;

    for (int k0 = 0; k0 < IN_LEN; k0 += 32) {
        // gather X tile: 128 rows x 32 k (float4 global reads, transposed smem store)
#pragma unroll
        for (int j = 0; j < 4; j++) {
            int idx = tid + j*256;
            int r = idx >> 3, kv = idx & 7;
            const float4 v = *(const float4*)(x + (size_t)s_tok[r]*IN_LEN + k0 + kv*4);
            Xs[kv*4+0][r] = v.x; Xs[kv*4+1][r] = v.y;
            Xs[kv*4+2][r] = v.z; Xs[kv*4+3][r] = v.w;
        }
        // W tile: 32 k x 64 cols
#pragma unroll
        for (int j = 0; j < 2; j++) {
            int idx = tid + j*256;
            int ccv = idx & 15, kk = idx >> 4;
            *(float4*)&Ws[kk][ccv*4] =
                *(const float4*)(wb0 + (size_t)(k0 + kk)*OUT_LEN + ccv*4);
        }
        __syncthreads();
#pragma unroll 8
        for (int kk = 0; kk < 32; kk++) {
            float4 xa = *(const float4*)&Xs[kk][ty*8];
            float4 xb = *(const float4*)&Xs[kk][ty*8 + 4];
            float4 w  = *(const float4*)&Ws[kk][tx*4];
            float xr[8] = {xa.x, xa.y, xa.z, xa.w, xb.x, xb.y, xb.z, xb.w};
            float wc[4] = {w.x, w.y, w.z, w.w};
#pragma unroll
            for (int i = 0; i < 8; i++)
#pragma unroll
                for (int j = 0; j < 4; j++)
                    acc[i][j] = fmaf(xr[i], wc[j], acc[i][j]);
        }
        __syncthreads();
    }
    // epilogue: scale by rw*gam and store to staging (no atomics)
#pragma unroll
    for (int i = 0; i < 8; i++) {
        int r = ty*8 + i;
        if (r < nrows) {
            float c = s_coef[r];
            float4 v = make_float4(c*acc[i][0], c*acc[i][1], c*acc[i][2], c*acc[i][3]);
            *(float4*)(g_stage + (size_t)(rbase + r)*OUT_LEN + cbase + tx*4) = v;
        }
    }
}

// ---------------- K7: compose out = rw0*bet[e0] + rw1*bet[e1] + stage0 + stage1 ----------------
__global__ void k_final(float* __restrict__ out) {
    int t = blockIdx.x;
    int i = threadIdx.x;   // 128 threads, float4 each
    int e0 = g_sel[2*t], e1 = g_sel[2*t+1];
    float r0 = g_rw[2*t], r1 = g_rw[2*t+1];
    int s0 = g_tslot[2*t], s1 = g_tslot[2*t+1];
    float4 b0 = *(const float4*)(g_bet + e0*OUT_LEN + i*4);
    float4 b1 = *(const float4*)(g_bet + e1*OUT_LEN + i*4);
    float4 a0 = *(const float4*)(g_stage + (size_t)s0*OUT_LEN + i*4);
    float4 a1 = *(const float4*)(g_stage + (size_t)s1*OUT_LEN + i*4);
    float4 o;
    o.x = fmaf(r0, b0.x, fmaf(r1, b1.x, a0.x + a1.x));
    o.y = fmaf(r0, b0.y, fmaf(r1, b1.y, a0.y + a1.y));
    o.z = fmaf(r0, b0.z, fmaf(r1, b1.z, a0.z + a1.z));
    o.w = fmaf(r0, b0.w, fmaf(r1, b1.w, a0.w + a1.w));
    *(float4*)(out + (size_t)t*OUT_LEN + i*4) = o;
}

// ---------------- launch ----------------
extern "C" void kernel_launch(void* const* d_in, const int* in_sizes, int n_in,
                              void* d_out, int out_size) {
    const float* x      = (const float*)d_in[0];  // (1, 8192, 512)
    const float* ins    = (const float*)d_in[1];  // (1, 16, 512)
    const float* gatew  = (const float*)d_in[2];  // (512, 8)
    const float* ew     = (const float*)d_in[3];  // (8, 512, 512)
    const float* eb     = (const float*)d_in[4];  // (8, 512)
    const float* gammaw = (const float*)d_in[5];  // (8, 512)
    const float* betaw  = (const float*)d_in[6];  // (8, 512, 512)
    const float* rmod   = (const float*)d_in[7];  // (512, 8)
    float* out = (float*)d_out;

    k_prep   <<<1, 512>>>(ins, rmod, gammaw);
    k_beta   <<<dim3(NE, OUT_LEN/128), 128>>>(betaw, eb);
    k_route  <<<N_TOK/8, 256>>>(x, gatew);
    k_offsets<<<1, 32>>>();
    k_scatter<<<N_TOK/256, 256>>>();
    k_gemm   <<<dim3(MAX_TILES, OUT_LEN/64), 256>>>(x, ew);
    k_final  <<<N_TOK, 128>>>(out);
}

// round 3
// speedup vs baseline: 1.4212x; 1.4212x over previous
#include <cuda_runtime.h>
#include <cuda_bf16.h>
#include <math.h>
#include <stdint.h>

#define N_TOK   8192
#define IN_LEN  512
#define OUT_LEN 512
#define NE      8
#define NI      16
#define NPAIR   (N_TOK*2)
#define MAX_TILES (NPAIR/128 + NE)   // 136

// ---------------- device scratch ----------------
__device__ float g_mean_ins[OUT_LEN];
__device__ float g_rgamma[NE];
__device__ float g_gam[NE];
__device__ float g_bet[NE*OUT_LEN];
__device__ int   g_sel[NPAIR];
__device__ float g_rw[NPAIR];
__device__ int   g_count[NE];
__device__ int   g_off[NE];
__device__ int   g_cursor[NE];
__device__ int   g_tile_start[NE+1];
__device__ int   g_list[NPAIR];
__device__ float g_lcoef[NPAIR];
__device__ int   g_tslot[NPAIR];
__device__ float g_stage[(size_t)NPAIR*OUT_LEN];
// pre-split weights [E, N(out), K(in)] bf16 hi/lo ; pre-split x [N_TOK, K]
__device__ __nv_bfloat16 g_wh[(size_t)NE*OUT_LEN*IN_LEN];
__device__ __nv_bfloat16 g_wl[(size_t)NE*OUT_LEN*IN_LEN];
__device__ __nv_bfloat16 g_xh[(size_t)N_TOK*IN_LEN];
__device__ __nv_bfloat16 g_xl[(size_t)N_TOK*IN_LEN];

// ---------------- PTX helpers (sm_80-generic: no tcgen05 — ptxas targets sm_103) ----
__device__ __forceinline__ uint32_t smem_u32(const void* p) {
    uint32_t a;
    asm("{ .reg .u64 t; cvta.to.shared.u64 t, %1; cvt.u32.u64 %0, t; }" : "=r"(a) : "l"(p));
    return a;
}
__device__ __forceinline__ void cpasync16(uint32_t dst, const void* src) {
    asm volatile("cp.async.cg.shared.global [%0], [%1], 16;" :: "r"(dst), "l"(src));
}
__device__ __forceinline__ void cp_commit() { asm volatile("cp.async.commit_group;" ::: "memory"); }
__device__ __forceinline__ void ldsm4(uint32_t* r, uint32_t addr) {
    asm volatile("ldmatrix.sync.aligned.m8n8.x4.shared.b16 {%0,%1,%2,%3}, [%4];"
                 : "=r"(r[0]), "=r"(r[1]), "=r"(r[2]), "=r"(r[3]) : "r"(addr));
}
__device__ __forceinline__ void mma16816(float* d, const uint32_t* a, const uint32_t* b) {
    asm volatile(
        "mma.sync.aligned.m16n8k16.row.col.f32.bf16.bf16.f32 "
        "{%0,%1,%2,%3}, {%4,%5,%6,%7}, {%8,%9}, {%0,%1,%2,%3};"
        : "+f"(d[0]), "+f"(d[1]), "+f"(d[2]), "+f"(d[3])
        : "r"(a[0]), "r"(a[1]), "r"(a[2]), "r"(a[3]), "r"(b[0]), "r"(b[1]));
}

// ---------------- K1 ----------------
__global__ void k_prep(const float* __restrict__ ins,
                       const float* __restrict__ rmod,
                       const float* __restrict__ gammaw) {
    int h = threadIdx.x;
    float s = 0.f;
#pragma unroll
    for (int n = 0; n < NI; n++) s += ins[n*OUT_LEN + h];
    s *= (1.f/NI);
    g_mean_ins[h] = s;
    __shared__ float sm[OUT_LEN];
    sm[h] = s;
    if (h < NE) g_count[h] = 0;
    __syncthreads();
    if (h < NE) {
        float a = 0.f, b = 0.f;
        for (int k = 0; k < OUT_LEN; k++) {
            float m = sm[k];
            a += m * rmod[k*NE + h];
            b += m * gammaw[h*OUT_LEN + k];
        }
        g_rgamma[h] = a;
        g_gam[h]    = b;
    }
}

// ---------------- K2: bet_eff ----------------
__global__ void k_beta(const float* __restrict__ betaw,
                       const float* __restrict__ eb) {
    int e = blockIdx.x;
    int d = blockIdx.y*128 + threadIdx.x;
    const float* bw = betaw + (size_t)e*OUT_LEN*OUT_LEN + d;
    float s = 0.f;
#pragma unroll 8
    for (int h = 0; h < OUT_LEN; h++) s += g_mean_ins[h] * bw[(size_t)h*OUT_LEN];
    g_bet[e*OUT_LEN + d] = s + g_gam[e] * eb[e*OUT_LEN + d];
}

// ---------------- K_convw: expert_w [E,K,N] -> split bf16 [E,N,K] ----------------
__global__ void k_convw(const float* __restrict__ ew) {
    __shared__ float t[32][33];
    int e = blockIdx.x, nb = blockIdx.y*32, kb = blockIdx.z*32;
    const float* src = ew + ((size_t)e*IN_LEN + kb)*OUT_LEN + nb;
#pragma unroll
    for (int i = threadIdx.y; i < 32; i += 8)
        t[i][threadIdx.x] = src[(size_t)i*OUT_LEN + threadIdx.x];
    __syncthreads();
#pragma unroll
    for (int i = threadIdx.y; i < 32; i += 8) {
        float v = t[threadIdx.x][i];
        __nv_bfloat16 h = __float2bfloat16(v);
        __nv_bfloat16 l = __float2bfloat16(v - __bfloat162float(h));
        size_t o = ((size_t)e*OUT_LEN + nb + i)*IN_LEN + kb + threadIdx.x;
        g_wh[o] = h;
        g_wl[o] = l;
    }
}

// ---------------- K3: routing + x split ----------------
__global__ void k_route(const float* __restrict__ x,
                        const float* __restrict__ gatew) {
    int warp = threadIdx.x >> 5;
    int lane = threadIdx.x & 31;
    int t = blockIdx.x*8 + warp;
    const float* xr = x + (size_t)t*IN_LEN;
    float acc[NE];
#pragma unroll
    for (int e = 0; e < NE; e++) acc[e] = 0.f;
    for (int i = 0; i < IN_LEN/32; i++) {
        float xv = xr[i*32 + lane];
        // split x into bf16 hi/lo for the tensor-core GEMM
        __nv_bfloat16 hh = __float2bfloat16(xv);
        __nv_bfloat16 ll = __float2bfloat16(xv - __bfloat162float(hh));
        g_xh[(size_t)t*IN_LEN + i*32 + lane] = hh;
        g_xl[(size_t)t*IN_LEN + i*32 + lane] = ll;
        const float* gw = gatew + (size_t)(i*32 + lane)*NE;
#pragma unroll
        for (int e = 0; e < NE; e++) acc[e] = fmaf(xv, gw[e], acc[e]);
    }
#pragma unroll
    for (int e = 0; e < NE; e++)
#pragma unroll
        for (int o = 16; o > 0; o >>= 1)
            acc[e] += __shfl_xor_sync(0xffffffffu, acc[e], o);
    if (lane == 0) {
        float l[NE];
#pragma unroll
        for (int e = 0; e < NE; e++) l[e] = acc[e] + g_rgamma[e];
        float m = l[0];
#pragma unroll
        for (int e = 1; e < NE; e++) m = fmaxf(m, l[e]);
        float s = 0.f;
#pragma unroll
        for (int e = 0; e < NE; e++) s += expf(l[e] - m);
        float inv = 1.f / s;
        int e0 = 0; float v0 = l[0];
#pragma unroll
        for (int e = 1; e < NE; e++) if (l[e] > v0) { v0 = l[e]; e0 = e; }
        int e1 = -1; float v1 = -INFINITY;
#pragma unroll
        for (int e = 0; e < NE; e++) if (e != e0 && l[e] > v1) { v1 = l[e]; e1 = e; }
        g_sel[2*t]   = e0;  g_sel[2*t+1] = e1;
        g_rw[2*t]    = expf(v0 - m) * inv;
        g_rw[2*t+1]  = expf(v1 - m) * inv;
        atomicAdd(&g_count[e0], 1);
        atomicAdd(&g_count[e1], 1);
    }
}

// ---------------- K4: offsets ----------------
__global__ void k_offsets() {
    if (threadIdx.x == 0 && blockIdx.x == 0) {
        int off = 0, ts = 0;
        for (int e = 0; e < NE; e++) {
            g_off[e] = off;
            g_tile_start[e] = ts;
            g_cursor[e] = 0;
            off += g_count[e];
            ts  += (g_count[e] + 127) >> 7;
        }
        g_tile_start[NE] = ts;
    }
}

// ---------------- K5: scatter ----------------
__global__ void k_scatter() {
    int t = blockIdx.x*blockDim.x + threadIdx.x;
    if (t >= N_TOK) return;
#pragma unroll
    for (int k = 0; k < 2; k++) {
        int e = g_sel[2*t + k];
        float rw = g_rw[2*t + k];
        int slot = g_off[e] + atomicAdd(&g_cursor[e], 1);
        g_list[slot]  = t;
        g_lcoef[slot] = rw * g_gam[e];
        g_tslot[2*t + k] = slot;
    }
}

// ---------------- K6: HMMA grouped GEMM 128x128, BK=32, split-bf16, 4-stage cp.async ----
#define BK        32
#define NCH       (IN_LEN/BK)      // 16
#define STAGES    4
#define ST_AH     0
#define ST_AL     8192
#define ST_BH     16384
#define ST_BL     24576
#define ST_SIZE   32768
#define OFF_TOK   (STAGES*ST_SIZE)            // 131072
#define OFF_COEF  (OFF_TOK + 512)
#define DYN_SMEM  (OFF_COEF + 512)            // 132096

// swizzled in-tile byte offset for (row, 16B-chunk c in 0..3); rows are 64B
__device__ __forceinline__ uint32_t tile_off(int row, int c) {
    return (uint32_t)(row*64 + ((c ^ ((row >> 1) & 3)) << 4));
}

__global__ __launch_bounds__(256) void k_gemm_tc(void) {
    extern __shared__ char smem[];
    int rt = blockIdx.x;
    int total = g_tile_start[NE];
    if (rt >= total) return;
    int e = 0;
#pragma unroll
    for (int i = 1; i < NE; i++) if (g_tile_start[i] <= rt) e = i;
    int tile_in_e = rt - g_tile_start[e];
    int rbase = g_off[e] + tile_in_e*128;
    int nrows = g_count[e] - tile_in_e*128;
    if (nrows > 128) nrows = 128;
    int cbase = blockIdx.y*128;

    uint32_t sb = smem_u32(smem);
    int tid = threadIdx.x;
    int lane = tid & 31;
    int wid = tid >> 5;
    int wm = wid >> 1;       // 0..3 -> warp M offset wm*32
    int wn = wid & 1;        // 0..1 -> warp N offset wn*64

    int*   s_tok  = (int*)(smem + OFF_TOK);
    float* s_coef = (float*)(smem + OFF_COEF);
    if (tid < 128) {
        s_tok[tid]  = (tid < nrows) ? g_list[rbase + tid]  : g_list[rbase];
        s_coef[tid] = (tid < nrows) ? g_lcoef[rbase + tid] : 0.f;
    }
    __syncthreads();

    const __nv_bfloat16* whp = g_wh + ((size_t)e*OUT_LEN + cbase)*IN_LEN;
    const __nv_bfloat16* wlp = g_wl + ((size_t)e*OUT_LEN + cbase)*IN_LEN;

    // per-thread load slots: idx -> (row = idx>>2, chunk c = idx&3), 2 slots per tensor
    int r0 = tid >> 2,        c0 = tid & 3;
    int r1 = (tid + 256) >> 2, c1 = tid & 3;   // (tid+256)&3 == tid&3
    int t0 = s_tok[r0], t1 = s_tok[r1];
    uint32_t dA0 = tile_off(r0, c0), dA1 = tile_off(r1, c1);

    // prologue: stages 0..2
#pragma unroll
    for (int pc = 0; pc < STAGES-1; pc++) {
        uint32_t st = sb + pc*ST_SIZE;
        int k0 = pc*BK;
        cpasync16(st + ST_AH + dA0, g_xh + (size_t)t0*IN_LEN + k0 + c0*8);
        cpasync16(st + ST_AH + dA1, g_xh + (size_t)t1*IN_LEN + k0 + c1*8);
        cpasync16(st + ST_AL + dA0, g_xl + (size_t)t0*IN_LEN + k0 + c0*8);
        cpasync16(st + ST_AL + dA1, g_xl + (size_t)t1*IN_LEN + k0 + c1*8);
        cpasync16(st + ST_BH + dA0, whp + (size_t)r0*IN_LEN + k0 + c0*8);
        cpasync16(st + ST_BH + dA1, whp + (size_t)r1*IN_LEN + k0 + c1*8);
        cpasync16(st + ST_BL + dA0, wlp + (size_t)r0*IN_LEN + k0 + c0*8);
        cpasync16(st + ST_BL + dA1, wlp + (size_t)r1*IN_LEN + k0 + c1*8);
        cp_commit();
    }

    float acc[2][8][4];
#pragma unroll
    for (int mb = 0; mb < 2; mb++)
#pragma unroll
        for (int nb = 0; nb < 8; nb++)
#pragma unroll
            for (int j = 0; j < 4; j++) acc[mb][nb][j] = 0.f;

    int j4 = lane >> 3, l7 = lane & 7;

    for (int ch = 0; ch < NCH; ch++) {
        asm volatile("cp.async.wait_group %0;" :: "n"(STAGES-2));
        __syncthreads();
        int nf = ch + STAGES - 1;
        if (nf < NCH) {
            uint32_t st = sb + (nf % STAGES)*ST_SIZE;
            int k0 = nf*BK;
            cpasync16(st + ST_AH + dA0, g_xh + (size_t)t0*IN_LEN + k0 + c0*8);
            cpasync16(st + ST_AH + dA1, g_xh + (size_t)t1*IN_LEN + k0 + c1*8);
            cpasync16(st + ST_AL + dA0, g_xl + (size_t)t0*IN_LEN + k0 + c0*8);
            cpasync16(st + ST_AL + dA1, g_xl + (size_t)t1*IN_LEN + k0 + c1*8);
            cpasync16(st + ST_BH + dA0, whp + (size_t)r0*IN_LEN + k0 + c0*8);
            cpasync16(st + ST_BH + dA1, whp + (size_t)r1*IN_LEN + k0 + c1*8);
            cpasync16(st + ST_BL + dA0, wlp + (size_t)r0*IN_LEN + k0 + c0*8);
            cpasync16(st + ST_BL + dA1, wlp + (size_t)r1*IN_LEN + k0 + c1*8);
        }
        cp_commit();

        uint32_t st = sb + (ch % STAGES)*ST_SIZE;
#pragma unroll
        for (int k16 = 0; k16 < 2; k16++) {
            uint32_t ah[2][4], al[2][4], bh[4][4], bl[4][4];
            // A frags: 16 rows each, matrices (mlow,klow)(mhigh,klow)(mlow,khigh)(mhigh,khigh)
#pragma unroll
            for (int mb = 0; mb < 2; mb++) {
                int row = wm*32 + mb*16 + ((j4 & 1) << 3) + l7;
                int c   = k16*2 + (j4 >> 1);
                uint32_t o = tile_off(row, c);
                ldsm4(ah[mb], st + ST_AH + o);
                ldsm4(al[mb], st + ST_AL + o);
            }
            // B frags: pair p covers n-blocks 2p,2p+1; matrices (nlow,klow)(nlow,khigh)(nhigh,klow)(nhigh,khigh)
#pragma unroll
            for (int p = 0; p < 4; p++) {
                int row = wn*64 + p*16 + ((j4 >> 1) << 3) + l7;
                int c   = k16*2 + (j4 & 1);
                uint32_t o = tile_off(row, c);
                ldsm4(bh[p], st + ST_BH + o);
                ldsm4(bl[p], st + ST_BL + o);
            }
#pragma unroll
            for (int mb = 0; mb < 2; mb++)
#pragma unroll
                for (int nb = 0; nb < 8; nb++) {
                    const uint32_t* pbh = &bh[nb >> 1][(nb & 1) * 2];
                    const uint32_t* pbl = &bl[nb >> 1][(nb & 1) * 2];
                    mma16816(acc[mb][nb], ah[mb], pbh);
                    mma16816(acc[mb][nb], ah[mb], pbl);
                    mma16816(acc[mb][nb], al[mb], pbh);
                }
        }
    }

    // epilogue: scale by rw*gam, store float2 pairs to staging
    int rl_lo = wm*32 + (lane >> 2);        // +mb*16, +8 for d2/d3
    int cc    = cbase + wn*64 + (lane & 3)*2;
#pragma unroll
    for (int mb = 0; mb < 2; mb++) {
#pragma unroll
        for (int half = 0; half < 2; half++) {
            int rl = rl_lo + mb*16 + half*8;
            if (rl < nrows) {
                float cf = s_coef[rl];
                float* dst = g_stage + (size_t)(rbase + rl)*OUT_LEN + cc;
#pragma unroll
                for (int nb = 0; nb < 8; nb++) {
                    float2 v = make_float2(cf*acc[mb][nb][half*2], cf*acc[mb][nb][half*2+1]);
                    *(float2*)(dst + nb*8) = v;
                }
            }
        }
    }
}

// ---------------- K7: compose ----------------
__global__ void k_final(float* __restrict__ out) {
    int t = blockIdx.x;
    int i = threadIdx.x;
    int e0 = g_sel[2*t], e1 = g_sel[2*t+1];
    float r0 = g_rw[2*t], r1 = g_rw[2*t+1];
    int s0 = g_tslot[2*t], s1 = g_tslot[2*t+1];
    float4 b0 = *(const float4*)(g_bet + e0*OUT_LEN + i*4);
    float4 b1 = *(const float4*)(g_bet + e1*OUT_LEN + i*4);
    float4 a0 = *(const float4*)(g_stage + (size_t)s0*OUT_LEN + i*4);
    float4 a1 = *(const float4*)(g_stage + (size_t)s1*OUT_LEN + i*4);
    float4 o;
    o.x = fmaf(r0, b0.x, fmaf(r1, b1.x, a0.x + a1.x));
    o.y = fmaf(r0, b0.y, fmaf(r1, b1.y, a0.y + a1.y));
    o.z = fmaf(r0, b0.z, fmaf(r1, b1.z, a0.z + a1.z));
    o.w = fmaf(r0, b0.w, fmaf(r1, b1.w, a0.w + a1.w));
    *(float4*)(out + (size_t)t*OUT_LEN + i*4) = o;
}

// ---------------- launch ----------------
extern "C" void kernel_launch(void* const* d_in, const int* in_sizes, int n_in,
                              void* d_out, int out_size) {
    const float* x      = (const float*)d_in[0];
    const float* ins    = (const float*)d_in[1];
    const float* gatew  = (const float*)d_in[2];
    const float* ew     = (const float*)d_in[3];
    const float* eb     = (const float*)d_in[4];
    const float* gammaw = (const float*)d_in[5];
    const float* betaw  = (const float*)d_in[6];
    const float* rmod   = (const float*)d_in[7];
    float* out = (float*)d_out;

    cudaFuncSetAttribute(k_gemm_tc, cudaFuncAttributeMaxDynamicSharedMemorySize, DYN_SMEM);

    k_convw  <<<dim3(NE, OUT_LEN/32, IN_LEN/32), dim3(32, 8)>>>(ew);
    k_prep   <<<1, 512>>>(ins, rmod, gammaw);
    k_beta   <<<dim3(NE, OUT_LEN/128), 128>>>(betaw, eb);
    k_route  <<<N_TOK/8, 256>>>(x, gatew);
    k_offsets<<<1, 32>>>();
    k_scatter<<<N_TOK/256, 256>>>();
    k_gemm_tc<<<dim3(MAX_TILES, OUT_LEN/128), 256, DYN_SMEM>>>();
    k_final  <<<N_TOK, 128>>>(out);
}

// round 4
// speedup vs baseline: 1.7716x; 1.2466x over previous
#include <cuda_runtime.h>
#include <cuda_bf16.h>
#include <math.h>
#include <stdint.h>

#define N_TOK   8192
#define IN_LEN  512
#define OUT_LEN 512
#define NE      8
#define NI      16
#define NPAIR   (N_TOK*2)
#define MAX_TILES (NPAIR/128 + NE)   // 136

// ---------------- device scratch ----------------
__device__ float g_mean_ins[OUT_LEN];
__device__ float g_rgamma[NE];
__device__ float g_gam[NE];
__device__ float g_bet[NE*OUT_LEN];
__device__ int   g_sel[NPAIR];
__device__ float g_rw[NPAIR];
__device__ int   g_count[NE];
__device__ int   g_cursor[NE];
__device__ int   g_list[NPAIR];
__device__ float g_lcoef[NPAIR];
__device__ int   g_tslot[NPAIR];
__device__ float g_stage[(size_t)NPAIR*OUT_LEN];
__device__ __nv_bfloat16 g_wh[(size_t)NE*OUT_LEN*IN_LEN];
__device__ __nv_bfloat16 g_wl[(size_t)NE*OUT_LEN*IN_LEN];
__device__ __nv_bfloat16 g_xh[(size_t)N_TOK*IN_LEN];
__device__ __nv_bfloat16 g_xl[(size_t)N_TOK*IN_LEN];

// ---------------- PTX helpers (sm_80-generic; ptxas targets plain sm_103) ----------
__device__ __forceinline__ uint32_t smem_u32(const void* p) {
    uint32_t a;
    asm("{ .reg .u64 t; cvta.to.shared.u64 t, %1; cvt.u32.u64 %0, t; }" : "=r"(a) : "l"(p));
    return a;
}
__device__ __forceinline__ void cpasync16(uint32_t dst, const void* src) {
    asm volatile("cp.async.cg.shared.global [%0], [%1], 16;" :: "r"(dst), "l"(src));
}
__device__ __forceinline__ void cp_commit() { asm volatile("cp.async.commit_group;" ::: "memory"); }
__device__ __forceinline__ void ldsm4(uint32_t* r, uint32_t addr) {
    asm volatile("ldmatrix.sync.aligned.m8n8.x4.shared.b16 {%0,%1,%2,%3}, [%4];"
                 : "=r"(r[0]), "=r"(r[1]), "=r"(r[2]), "=r"(r[3]) : "r"(addr));
}
__device__ __forceinline__ void mma16816(float* d, const uint32_t* a, const uint32_t* b) {
    asm volatile(
        "mma.sync.aligned.m16n8k16.row.col.f32.bf16.bf16.f32 "
        "{%0,%1,%2,%3}, {%4,%5,%6,%7}, {%8,%9}, {%0,%1,%2,%3};"
        : "+f"(d[0]), "+f"(d[1]), "+f"(d[2]), "+f"(d[3])
        : "r"(a[0]), "r"(a[1]), "r"(a[2]), "r"(a[3]), "r"(b[0]), "r"(b[1]));
}
__device__ __forceinline__ uint32_t pkbf(float a, float b) {
    __nv_bfloat16 ha = __float2bfloat16(a), hb = __float2bfloat16(b);
    return (uint32_t)__bfloat16_as_ushort(ha) | ((uint32_t)__bfloat16_as_ushort(hb) << 16);
}

// ---------------- K1: mean_ins, rgamma, gam; zero counters ----------------
__global__ void k_prep(const float* __restrict__ ins,
                       const float* __restrict__ rmod,
                       const float* __restrict__ gammaw) {
    int h = threadIdx.x;
    float s = 0.f;
#pragma unroll
    for (int n = 0; n < NI; n++) s += ins[n*OUT_LEN + h];
    s *= (1.f/NI);
    g_mean_ins[h] = s;
    __shared__ float sm[OUT_LEN];
    sm[h] = s;
    if (h < NE) { g_count[h] = 0; g_cursor[h] = 0; }
    __syncthreads();
    if (h < NE) {
        float a = 0.f, b = 0.f;
        for (int k = 0; k < OUT_LEN; k++) {
            float m = sm[k];
            a += m * rmod[k*NE + h];
            b += m * gammaw[h*OUT_LEN + k];
        }
        g_rgamma[h] = a;
        g_gam[h]    = b;
    }
}

// ---------------- K2: bet_eff, 512 threads, 4-way h-split ----------------
__global__ __launch_bounds__(512) void k_beta(const float* __restrict__ betaw,
                                              const float* __restrict__ eb) {
    int e  = blockIdx.x;
    int d  = blockIdx.y*128 + (threadIdx.x & 127);
    int hg = threadIdx.x >> 7;   // 0..3
    const float* bw = betaw + (size_t)e*OUT_LEN*OUT_LEN + d;
    float s = 0.f;
#pragma unroll 8
    for (int h = hg*128; h < hg*128 + 128; h++)
        s += g_mean_ins[h] * bw[(size_t)h*OUT_LEN];
    __shared__ float red[512];
    red[threadIdx.x] = s;
    __syncthreads();
    if (hg == 0) {
        float tot = red[threadIdx.x] + red[threadIdx.x+128]
                  + red[threadIdx.x+256] + red[threadIdx.x+384];
        g_bet[e*OUT_LEN + d] = tot + g_gam[e] * eb[e*OUT_LEN + d];
    }
}

// ---------------- K_convw: expert_w [E,K,N] -> split bf16 [E,N,K], packed writes ----
__global__ __launch_bounds__(256) void k_convw(const float* __restrict__ ew) {
    __shared__ float t[32][33];
    int e = blockIdx.x, nb = blockIdx.y*32, kb = blockIdx.z*32;
    int tx = threadIdx.x & 31, ty = threadIdx.x >> 5;   // 32 x 8
    const float* src = ew + ((size_t)e*IN_LEN + kb)*OUT_LEN + nb;
#pragma unroll
    for (int i = ty; i < 32; i += 8)
        t[i][tx] = src[(size_t)i*OUT_LEN + tx];
    __syncthreads();
    int r  = threadIdx.x >> 3;   // n-row 0..31
    int kq = threadIdx.x & 7;    // 4 k's per thread
    float v0 = t[kq*4+0][r], v1 = t[kq*4+1][r], v2 = t[kq*4+2][r], v3 = t[kq*4+3][r];
    __nv_bfloat16 h0 = __float2bfloat16(v0), h1 = __float2bfloat16(v1);
    __nv_bfloat16 h2 = __float2bfloat16(v2), h3 = __float2bfloat16(v3);
    uint2 hp = make_uint2(
        (uint32_t)__bfloat16_as_ushort(h0) | ((uint32_t)__bfloat16_as_ushort(h1) << 16),
        (uint32_t)__bfloat16_as_ushort(h2) | ((uint32_t)__bfloat16_as_ushort(h3) << 16));
    uint2 lp = make_uint2(
        pkbf(v0 - __bfloat162float(h0), v1 - __bfloat162float(h1)),
        pkbf(v2 - __bfloat162float(h2), v3 - __bfloat162float(h3)));
    size_t o = ((size_t)e*OUT_LEN + nb + r)*IN_LEN + kb + kq*4;
    *(uint2*)(g_wh + o) = hp;
    *(uint2*)(g_wl + o) = lp;
}

// ---------------- K3: routing + x split; gate_w transposed in smem ----------------
__global__ __launch_bounds__(256) void k_route(const float* __restrict__ x,
                                               const float* __restrict__ gatew) {
    __shared__ float sgw[NE][IN_LEN];   // 16 KB, transposed
    int tid = threadIdx.x;
    for (int i = tid; i < IN_LEN*NE; i += 256)
        sgw[i & 7][i >> 3] = gatew[i];
    __syncthreads();
    int lane = tid & 31, wid = tid >> 5;
#pragma unroll 1
    for (int tt = 0; tt < 4; tt++) {
        int t = blockIdx.x*32 + wid*4 + tt;
        const float4* xr = (const float4*)(x + (size_t)t*IN_LEN);
        float acc[NE];
#pragma unroll
        for (int e = 0; e < NE; e++) acc[e] = 0.f;
#pragma unroll
        for (int j = 0; j < 4; j++) {
            float4 v = xr[j*32 + lane];
            __nv_bfloat16 h0 = __float2bfloat16(v.x), h1 = __float2bfloat16(v.y);
            __nv_bfloat16 h2 = __float2bfloat16(v.z), h3 = __float2bfloat16(v.w);
            uint2 hp = make_uint2(
                (uint32_t)__bfloat16_as_ushort(h0) | ((uint32_t)__bfloat16_as_ushort(h1) << 16),
                (uint32_t)__bfloat16_as_ushort(h2) | ((uint32_t)__bfloat16_as_ushort(h3) << 16));
            uint2 lp = make_uint2(
                pkbf(v.x - __bfloat162float(h0), v.y - __bfloat162float(h1)),
                pkbf(v.z - __bfloat162float(h2), v.w - __bfloat162float(h3)));
            size_t xo = (size_t)t*IN_LEN + j*128 + lane*4;
            *(uint2*)(g_xh + xo) = hp;
            *(uint2*)(g_xl + xo) = lp;
#pragma unroll
            for (int e = 0; e < NE; e++) {
                float4 g = *(const float4*)&sgw[e][j*128 + lane*4];
                acc[e] += v.x*g.x + v.y*g.y + v.z*g.z + v.w*g.w;
            }
        }
#pragma unroll
        for (int e = 0; e < NE; e++)
#pragma unroll
            for (int o = 16; o > 0; o >>= 1)
                acc[e] += __shfl_xor_sync(0xffffffffu, acc[e], o);
        if (lane == 0) {
            float l[NE];
#pragma unroll
            for (int e = 0; e < NE; e++) l[e] = acc[e] + g_rgamma[e];
            float m = l[0];
#pragma unroll
            for (int e = 1; e < NE; e++) m = fmaxf(m, l[e]);
            float s = 0.f;
#pragma unroll
            for (int e = 0; e < NE; e++) s += expf(l[e] - m);
            float inv = 1.f / s;
            int e0 = 0; float v0 = l[0];
#pragma unroll
            for (int e = 1; e < NE; e++) if (l[e] > v0) { v0 = l[e]; e0 = e; }
            int e1 = -1; float v1 = -INFINITY;
#pragma unroll
            for (int e = 0; e < NE; e++) if (e != e0 && l[e] > v1) { v1 = l[e]; e1 = e; }
            g_sel[2*t]   = e0;  g_sel[2*t+1] = e1;
            g_rw[2*t]    = expf(v0 - m) * inv;
            g_rw[2*t+1]  = expf(v1 - m) * inv;
            atomicAdd(&g_count[e0], 1);
            atomicAdd(&g_count[e1], 1);
        }
    }
}

// ---------------- K5: scatter (prefix computed locally; no offsets kernel) --------
__global__ void k_scatter() {
    __shared__ int soff[NE];
    if (threadIdx.x < NE) {
        int off = 0;
        for (int i = 0; i < (int)threadIdx.x; i++) off += g_count[i];
        soff[threadIdx.x] = off;
    }
    __syncthreads();
    int t = blockIdx.x*blockDim.x + threadIdx.x;
    if (t >= N_TOK) return;
#pragma unroll
    for (int k = 0; k < 2; k++) {
        int e = g_sel[2*t + k];
        float rw = g_rw[2*t + k];
        int slot = soff[e] + atomicAdd(&g_cursor[e], 1);
        g_list[slot]  = t;
        g_lcoef[slot] = rw * g_gam[e];
        g_tslot[2*t + k] = slot;
    }
}

// ---------------- K6: HMMA grouped GEMM 128x128, BK=32, split-bf16, 4-stage ------
#define BK        32
#define NCH       (IN_LEN/BK)      // 16
#define STAGES    4
#define ST_AH     0
#define ST_AL     8192
#define ST_BH     16384
#define ST_BL     24576
#define ST_SIZE   32768
#define OFF_TOK   (STAGES*ST_SIZE)            // 131072
#define OFF_COEF  (OFF_TOK + 512)
#define DYN_SMEM  (OFF_COEF + 512)            // 132096

__device__ __forceinline__ uint32_t tile_off(int row, int c) {
    return (uint32_t)(row*64 + ((c ^ ((row >> 1) & 3)) << 4));
}

__global__ __launch_bounds__(256) void k_gemm_tc(void) {
    extern __shared__ char smem[];
    int rt = blockIdx.x;
    // local prefix over 8 expert counts
    int e = -1, rbase = 0, nrows = 0;
    {
        int ts = 0, off = 0;
#pragma unroll
        for (int i = 0; i < NE; i++) {
            int cnt = g_count[i];
            int ti = (cnt + 127) >> 7;
            if (e < 0 && rt < ts + ti) {
                int tie = rt - ts;
                e = i; rbase = off + tie*128; nrows = cnt - tie*128;
            }
            ts += ti; off += cnt;
        }
    }
    if (e < 0) return;
    if (nrows > 128) nrows = 128;
    int cbase = blockIdx.y*128;

    uint32_t sb = smem_u32(smem);
    int tid = threadIdx.x;
    int lane = tid & 31;
    int wid = tid >> 5;
    int wm = wid >> 1;
    int wn = wid & 1;

    int*   s_tok  = (int*)(smem + OFF_TOK);
    float* s_coef = (float*)(smem + OFF_COEF);
    if (tid < 128) {
        s_tok[tid]  = (tid < nrows) ? g_list[rbase + tid]  : g_list[rbase];
        s_coef[tid] = (tid < nrows) ? g_lcoef[rbase + tid] : 0.f;
    }
    __syncthreads();

    const __nv_bfloat16* whp = g_wh + ((size_t)e*OUT_LEN + cbase)*IN_LEN;
    const __nv_bfloat16* wlp = g_wl + ((size_t)e*OUT_LEN + cbase)*IN_LEN;

    int r0 = tid >> 2,         c0 = tid & 3;
    int r1 = (tid + 256) >> 2, c1 = tid & 3;
    int t0 = s_tok[r0], t1 = s_tok[r1];
    uint32_t dA0 = tile_off(r0, c0), dA1 = tile_off(r1, c1);

#pragma unroll
    for (int pc = 0; pc < STAGES-1; pc++) {
        uint32_t st = sb + pc*ST_SIZE;
        int k0 = pc*BK;
        cpasync16(st + ST_AH + dA0, g_xh + (size_t)t0*IN_LEN + k0 + c0*8);
        cpasync16(st + ST_AH + dA1, g_xh + (size_t)t1*IN_LEN + k0 + c1*8);
        cpasync16(st + ST_AL + dA0, g_xl + (size_t)t0*IN_LEN + k0 + c0*8);
        cpasync16(st + ST_AL + dA1, g_xl + (size_t)t1*IN_LEN + k0 + c1*8);
        cpasync16(st + ST_BH + dA0, whp + (size_t)r0*IN_LEN + k0 + c0*8);
        cpasync16(st + ST_BH + dA1, whp + (size_t)r1*IN_LEN + k0 + c1*8);
        cpasync16(st + ST_BL + dA0, wlp + (size_t)r0*IN_LEN + k0 + c0*8);
        cpasync16(st + ST_BL + dA1, wlp + (size_t)r1*IN_LEN + k0 + c1*8);
        cp_commit();
    }

    float acc[2][8][4];
#pragma unroll
    for (int mb = 0; mb < 2; mb++)
#pragma unroll
        for (int nb = 0; nb < 8; nb++)
#pragma unroll
            for (int j = 0; j < 4; j++) acc[mb][nb][j] = 0.f;

    int j4 = lane >> 3, l7 = lane & 7;

    for (int ch = 0; ch < NCH; ch++) {
        asm volatile("cp.async.wait_group %0;" :: "n"(STAGES-2));
        __syncthreads();
        int nf = ch + STAGES - 1;
        if (nf < NCH) {
            uint32_t st = sb + (nf % STAGES)*ST_SIZE;
            int k0 = nf*BK;
            cpasync16(st + ST_AH + dA0, g_xh + (size_t)t0*IN_LEN + k0 + c0*8);
            cpasync16(st + ST_AH + dA1, g_xh + (size_t)t1*IN_LEN + k0 + c1*8);
            cpasync16(st + ST_AL + dA0, g_xl + (size_t)t0*IN_LEN + k0 + c0*8);
            cpasync16(st + ST_AL + dA1, g_xl + (size_t)t1*IN_LEN + k0 + c1*8);
            cpasync16(st + ST_BH + dA0, whp + (size_t)r0*IN_LEN + k0 + c0*8);
            cpasync16(st + ST_BH + dA1, whp + (size_t)r1*IN_LEN + k0 + c1*8);
            cpasync16(st + ST_BL + dA0, wlp + (size_t)r0*IN_LEN + k0 + c0*8);
            cpasync16(st + ST_BL + dA1, wlp + (size_t)r1*IN_LEN + k0 + c1*8);
        }
        cp_commit();

        uint32_t st = sb + (ch % STAGES)*ST_SIZE;
#pragma unroll
        for (int k16 = 0; k16 < 2; k16++) {
            uint32_t ah[2][4], al[2][4], bh[4][4], bl[4][4];
#pragma unroll
            for (int mb = 0; mb < 2; mb++) {
                int row = wm*32 + mb*16 + ((j4 & 1) << 3) + l7;
                int c   = k16*2 + (j4 >> 1);
                uint32_t o = tile_off(row, c);
                ldsm4(ah[mb], st + ST_AH + o);
                ldsm4(al[mb], st + ST_AL + o);
            }
#pragma unroll
            for (int p = 0; p < 4; p++) {
                int row = wn*64 + p*16 + ((j4 >> 1) << 3) + l7;
                int c   = k16*2 + (j4 & 1);
                uint32_t o = tile_off(row, c);
                ldsm4(bh[p], st + ST_BH + o);
                ldsm4(bl[p], st + ST_BL + o);
            }
#pragma unroll
            for (int mb = 0; mb < 2; mb++)
#pragma unroll
                for (int nb = 0; nb < 8; nb++) {
                    const uint32_t* pbh = &bh[nb >> 1][(nb & 1) * 2];
                    const uint32_t* pbl = &bl[nb >> 1][(nb & 1) * 2];
                    mma16816(acc[mb][nb], ah[mb], pbh);
                    mma16816(acc[mb][nb], ah[mb], pbl);
                    mma16816(acc[mb][nb], al[mb], pbh);
                }
        }
    }

    int rl_lo = wm*32 + (lane >> 2);
    int cc    = cbase + wn*64 + (lane & 3)*2;
#pragma unroll
    for (int mb = 0; mb < 2; mb++) {
#pragma unroll
        for (int half = 0; half < 2; half++) {
            int rl = rl_lo + mb*16 + half*8;
            if (rl < nrows) {
                float cf = s_coef[rl];
                float* dst = g_stage + (size_t)(rbase + rl)*OUT_LEN + cc;
#pragma unroll
                for (int nb = 0; nb < 8; nb++) {
                    float2 v = make_float2(cf*acc[mb][nb][half*2], cf*acc[mb][nb][half*2+1]);
                    *(float2*)(dst + nb*8) = v;
                }
            }
        }
    }
}

// ---------------- K7: compose ----------------
__global__ void k_final(float* __restrict__ out) {
    int t = blockIdx.x;
    int i = threadIdx.x;
    int e0 = g_sel[2*t], e1 = g_sel[2*t+1];
    float r0 = g_rw[2*t], r1 = g_rw[2*t+1];
    int s0 = g_tslot[2*t], s1 = g_tslot[2*t+1];
    float4 b0 = *(const float4*)(g_bet + e0*OUT_LEN + i*4);
    float4 b1 = *(const float4*)(g_bet + e1*OUT_LEN + i*4);
    float4 a0 = *(const float4*)(g_stage + (size_t)s0*OUT_LEN + i*4);
    float4 a1 = *(const float4*)(g_stage + (size_t)s1*OUT_LEN + i*4);
    float4 o;
    o.x = fmaf(r0, b0.x, fmaf(r1, b1.x, a0.x + a1.x));
    o.y = fmaf(r0, b0.y, fmaf(r1, b1.y, a0.y + a1.y));
    o.z = fmaf(r0, b0.z, fmaf(r1, b1.z, a0.z + a1.z));
    o.w = fmaf(r0, b0.w, fmaf(r1, b1.w, a0.w + a1.w));
    *(float4*)(out + (size_t)t*OUT_LEN + i*4) = o;
}

// ---------------- launch ----------------
extern "C" void kernel_launch(void* const* d_in, const int* in_sizes, int n_in,
                              void* d_out, int out_size) {
    const float* x      = (const float*)d_in[0];
    const float* ins    = (const float*)d_in[1];
    const float* gatew  = (const float*)d_in[2];
    const float* ew     = (const float*)d_in[3];
    const float* eb     = (const float*)d_in[4];
    const float* gammaw = (const float*)d_in[5];
    const float* betaw  = (const float*)d_in[6];
    const float* rmod   = (const float*)d_in[7];
    float* out = (float*)d_out;

    cudaFuncSetAttribute(k_gemm_tc, cudaFuncAttributeMaxDynamicSharedMemorySize, DYN_SMEM);

    k_convw  <<<dim3(NE, OUT_LEN/32, IN_LEN/32), 256>>>(ew);
    k_prep   <<<1, 512>>>(ins, rmod, gammaw);
    k_beta   <<<dim3(NE, OUT_LEN/128), 512>>>(betaw, eb);
    k_route  <<<N_TOK/32, 256>>>(x, gatew);
    k_scatter<<<N_TOK/256, 256>>>();
    k_gemm_tc<<<dim3(MAX_TILES, OUT_LEN/128), 256, DYN_SMEM>>>();
    k_final  <<<N_TOK, 128>>>(out);
}

// round 5
// speedup vs baseline: 1.9301x; 1.0895x over previous
#include <cuda_runtime.h>
#include <cuda_bf16.h>
#include <math.h>
#include <stdint.h>

#define N_TOK   8192
#define IN_LEN  512
#define OUT_LEN 512
#define NE      8
#define NI      16
#define NPAIR   (N_TOK*2)
#define MAX_TILES (NPAIR/128 + NE)   // 136

// ---------------- device scratch ----------------
__device__ float g_mean_ins[OUT_LEN];
__device__ float g_rgamma[NE];
__device__ float g_gam[NE];
__device__ float g_bet[NE*OUT_LEN];
__device__ int   g_sel[NPAIR];
__device__ float g_rw[NPAIR];
__device__ int   g_count[NE];
__device__ int   g_cursor[NE];
__device__ int   g_list[NPAIR];
__device__ float g_lcoef[NPAIR];
__device__ int   g_tslot[NPAIR];
__device__ float g_stage[(size_t)NPAIR*OUT_LEN];
__device__ __nv_bfloat16 g_wh[(size_t)NE*OUT_LEN*IN_LEN];
__device__ __nv_bfloat16 g_wl[(size_t)NE*OUT_LEN*IN_LEN];
__device__ __nv_bfloat16 g_xh[(size_t)N_TOK*IN_LEN];
__device__ __nv_bfloat16 g_xl[(size_t)N_TOK*IN_LEN];

// ---------------- PTX helpers (sm_80-generic; ptxas targets plain sm_103) ----------
__device__ __forceinline__ uint32_t smem_u32(const void* p) {
    uint32_t a;
    asm("{ .reg .u64 t; cvta.to.shared.u64 t, %1; cvt.u32.u64 %0, t; }" : "=r"(a) : "l"(p));
    return a;
}
__device__ __forceinline__ void cpasync16(uint32_t dst, const void* src) {
    asm volatile("cp.async.cg.shared.global [%0], [%1], 16;" :: "r"(dst), "l"(src));
}
__device__ __forceinline__ void cp_commit() { asm volatile("cp.async.commit_group;" ::: "memory"); }
__device__ __forceinline__ void ldsm4(uint32_t* r, uint32_t addr) {
    asm volatile("ldmatrix.sync.aligned.m8n8.x4.shared.b16 {%0,%1,%2,%3}, [%4];"
                 : "=r"(r[0]), "=r"(r[1]), "=r"(r[2]), "=r"(r[3]) : "r"(addr));
}
__device__ __forceinline__ void mma16816(float* d, const uint32_t* a, const uint32_t* b) {
    asm volatile(
        "mma.sync.aligned.m16n8k16.row.col.f32.bf16.bf16.f32 "
        "{%0,%1,%2,%3}, {%4,%5,%6,%7}, {%8,%9}, {%0,%1,%2,%3};"
        : "+f"(d[0]), "+f"(d[1]), "+f"(d[2]), "+f"(d[3])
        : "r"(a[0]), "r"(a[1]), "r"(a[2]), "r"(a[3]), "r"(b[0]), "r"(b[1]));
}
__device__ __forceinline__ uint32_t pkbf(float a, float b) {
    __nv_bfloat16 ha = __float2bfloat16(a), hb = __float2bfloat16(b);
    return (uint32_t)__bfloat16_as_ushort(ha) | ((uint32_t)__bfloat16_as_ushort(hb) << 16);
}

// ---------------- K1: mean_ins, rgamma, gam; zero counters ----------------
__global__ void k_prep(const float* __restrict__ ins,
                       const float* __restrict__ rmod,
                       const float* __restrict__ gammaw) {
    int h = threadIdx.x;
    float s = 0.f;
#pragma unroll
    for (int n = 0; n < NI; n++) s += ins[n*OUT_LEN + h];
    s *= (1.f/NI);
    g_mean_ins[h] = s;
    __shared__ float sm[OUT_LEN];
    sm[h] = s;
    if (h < NE) { g_count[h] = 0; g_cursor[h] = 0; }
    __syncthreads();
    if (h < NE) {
        float a = 0.f, b = 0.f;
        for (int k = 0; k < OUT_LEN; k++) {
            float m = sm[k];
            a += m * rmod[k*NE + h];
            b += m * gammaw[h*OUT_LEN + k];
        }
        g_rgamma[h] = a;
        g_gam[h]    = b;
    }
}

// ---------------- K2: bet_eff, 512 threads, 4-way h-split ----------------
__global__ __launch_bounds__(512) void k_beta(const float* __restrict__ betaw,
                                              const float* __restrict__ eb) {
    int e  = blockIdx.x;
    int d  = blockIdx.y*128 + (threadIdx.x & 127);
    int hg = threadIdx.x >> 7;
    const float* bw = betaw + (size_t)e*OUT_LEN*OUT_LEN + d;
    float s = 0.f;
#pragma unroll 8
    for (int h = hg*128; h < hg*128 + 128; h++)
        s += g_mean_ins[h] * bw[(size_t)h*OUT_LEN];
    __shared__ float red[512];
    red[threadIdx.x] = s;
    __syncthreads();
    if (hg == 0) {
        float tot = red[threadIdx.x] + red[threadIdx.x+128]
                  + red[threadIdx.x+256] + red[threadIdx.x+384];
        g_bet[e*OUT_LEN + d] = tot + g_gam[e] * eb[e*OUT_LEN + d];
    }
}

// ---------------- K_convw: expert_w [E,K,N] -> split bf16 [E,N,K], packed writes ----
__global__ __launch_bounds__(256) void k_convw(const float* __restrict__ ew) {
    __shared__ float t[32][33];
    int e = blockIdx.x, nb = blockIdx.y*32, kb = blockIdx.z*32;
    int tx = threadIdx.x & 31, ty = threadIdx.x >> 5;
    const float* src = ew + ((size_t)e*IN_LEN + kb)*OUT_LEN + nb;
#pragma unroll
    for (int i = ty; i < 32; i += 8)
        t[i][tx] = src[(size_t)i*OUT_LEN + tx];
    __syncthreads();
    int r  = threadIdx.x >> 3;
    int kq = threadIdx.x & 7;
    float v0 = t[kq*4+0][r], v1 = t[kq*4+1][r], v2 = t[kq*4+2][r], v3 = t[kq*4+3][r];
    __nv_bfloat16 h0 = __float2bfloat16(v0), h1 = __float2bfloat16(v1);
    __nv_bfloat16 h2 = __float2bfloat16(v2), h3 = __float2bfloat16(v3);
    uint2 hp = make_uint2(
        (uint32_t)__bfloat16_as_ushort(h0) | ((uint32_t)__bfloat16_as_ushort(h1) << 16),
        (uint32_t)__bfloat16_as_ushort(h2) | ((uint32_t)__bfloat16_as_ushort(h3) << 16));
    uint2 lp = make_uint2(
        pkbf(v0 - __bfloat162float(h0), v1 - __bfloat162float(h1)),
        pkbf(v2 - __bfloat162float(h2), v3 - __bfloat162float(h3)));
    size_t o = ((size_t)e*OUT_LEN + nb + r)*IN_LEN + kb + kq*4;
    *(uint2*)(g_wh + o) = hp;
    *(uint2*)(g_wl + o) = lp;
}

// ---------------- K3: routing + x split; gate_w transposed in smem ----------------
__global__ __launch_bounds__(256, 3) void k_route(const float* __restrict__ x,
                                                  const float* __restrict__ gatew) {
    __shared__ float sgw[NE][IN_LEN];   // 16 KB, transposed
    int tid = threadIdx.x;
    for (int i = tid; i < IN_LEN*NE; i += 256)
        sgw[i & 7][i >> 3] = gatew[i];
    __syncthreads();
    int lane = tid & 31, wid = tid >> 5;
#pragma unroll 1
    for (int tt = 0; tt < 4; tt++) {
        int t = blockIdx.x*32 + wid*4 + tt;
        const float4* xr = (const float4*)(x + (size_t)t*IN_LEN);
        float acc[NE];
#pragma unroll
        for (int e = 0; e < NE; e++) acc[e] = 0.f;
#pragma unroll 2
        for (int j = 0; j < 4; j++) {
            float4 v = xr[j*32 + lane];
            __nv_bfloat16 h0 = __float2bfloat16(v.x), h1 = __float2bfloat16(v.y);
            __nv_bfloat16 h2 = __float2bfloat16(v.z), h3 = __float2bfloat16(v.w);
            uint2 hp = make_uint2(
                (uint32_t)__bfloat16_as_ushort(h0) | ((uint32_t)__bfloat16_as_ushort(h1) << 16),
                (uint32_t)__bfloat16_as_ushort(h2) | ((uint32_t)__bfloat16_as_ushort(h3) << 16));
            uint2 lp = make_uint2(
                pkbf(v.x - __bfloat162float(h0), v.y - __bfloat162float(h1)),
                pkbf(v.z - __bfloat162float(h2), v.w - __bfloat162float(h3)));
            size_t xo = (size_t)t*IN_LEN + j*128 + lane*4;
            *(uint2*)(g_xh + xo) = hp;
            *(uint2*)(g_xl + xo) = lp;
#pragma unroll
            for (int e = 0; e < NE; e++) {
                float4 g = *(const float4*)&sgw[e][j*128 + lane*4];
                acc[e] += v.x*g.x + v.y*g.y + v.z*g.z + v.w*g.w;
            }
        }
#pragma unroll
        for (int e = 0; e < NE; e++)
#pragma unroll
            for (int o = 16; o > 0; o >>= 1)
                acc[e] += __shfl_xor_sync(0xffffffffu, acc[e], o);
        if (lane == 0) {
            float l[NE];
#pragma unroll
            for (int e = 0; e < NE; e++) l[e] = acc[e] + g_rgamma[e];
            float m = l[0];
#pragma unroll
            for (int e = 1; e < NE; e++) m = fmaxf(m, l[e]);
            float s = 0.f;
#pragma unroll
            for (int e = 0; e < NE; e++) s += expf(l[e] - m);
            float inv = 1.f / s;
            int e0 = 0; float v0 = l[0];
#pragma unroll
            for (int e = 1; e < NE; e++) if (l[e] > v0) { v0 = l[e]; e0 = e; }
            int e1 = -1; float v1 = -INFINITY;
#pragma unroll
            for (int e = 0; e < NE; e++) if (e != e0 && l[e] > v1) { v1 = l[e]; e1 = e; }
            g_sel[2*t]   = e0;  g_sel[2*t+1] = e1;
            g_rw[2*t]    = expf(v0 - m) * inv;
            g_rw[2*t+1]  = expf(v1 - m) * inv;
            atomicAdd(&g_count[e0], 1);
            atomicAdd(&g_count[e1], 1);
        }
    }
}

// ---------------- K5: scatter (prefix computed locally) ----------------
__global__ void k_scatter() {
    __shared__ int soff[NE];
    if (threadIdx.x < NE) {
        int off = 0;
        for (int i = 0; i < (int)threadIdx.x; i++) off += g_count[i];
        soff[threadIdx.x] = off;
    }
    __syncthreads();
    int t = blockIdx.x*blockDim.x + threadIdx.x;
    if (t >= N_TOK) return;
#pragma unroll
    for (int k = 0; k < 2; k++) {
        int e = g_sel[2*t + k];
        float rw = g_rw[2*t + k];
        int slot = soff[e] + atomicAdd(&g_cursor[e], 1);
        g_list[slot]  = t;
        g_lcoef[slot] = rw * g_gam[e];
        g_tslot[2*t + k] = slot;
    }
}

// ---------------- K6: HMMA grouped GEMM 128x128, BK=32, split-bf16, 3-stage ------
#define BK        32
#define NCH       (IN_LEN/BK)      // 16
#define STAGES    3
#define ST_AH     0
#define ST_AL     8192
#define ST_BH     16384
#define ST_BL     24576
#define ST_SIZE   32768
#define OFF_TOK   (STAGES*ST_SIZE)            // 98304
#define OFF_COEF  (OFF_TOK + 512)
#define DYN_SMEM  (OFF_COEF + 512)            // 99328

__device__ __forceinline__ uint32_t tile_off(int row, int c) {
    return (uint32_t)(row*64 + ((c ^ ((row >> 1) & 3)) << 4));
}

__global__ __launch_bounds__(256, 2) void k_gemm_tc(void) {
    extern __shared__ char smem[];
    int rt = blockIdx.x;
    int e = -1, rbase = 0, nrows = 0;
    {
        int ts = 0, off = 0;
#pragma unroll
        for (int i = 0; i < NE; i++) {
            int cnt = g_count[i];
            int ti = (cnt + 127) >> 7;
            if (e < 0 && rt < ts + ti) {
                int tie = rt - ts;
                e = i; rbase = off + tie*128; nrows = cnt - tie*128;
            }
            ts += ti; off += cnt;
        }
    }
    if (e < 0) return;
    if (nrows > 128) nrows = 128;
    int cbase = blockIdx.y*128;

    uint32_t sb = smem_u32(smem);
    int tid = threadIdx.x;
    int lane = tid & 31;
    int wid = tid >> 5;
    int wm = wid >> 1;
    int wn = wid & 1;

    int*   s_tok  = (int*)(smem + OFF_TOK);
    float* s_coef = (float*)(smem + OFF_COEF);
    if (tid < 128) {
        s_tok[tid]  = (tid < nrows) ? g_list[rbase + tid]  : g_list[rbase];
        s_coef[tid] = (tid < nrows) ? g_lcoef[rbase + tid] : 0.f;
    }
    __syncthreads();

    const __nv_bfloat16* whp = g_wh + ((size_t)e*OUT_LEN + cbase)*IN_LEN;
    const __nv_bfloat16* wlp = g_wl + ((size_t)e*OUT_LEN + cbase)*IN_LEN;

    int r0 = tid >> 2,         c0 = tid & 3;
    int r1 = (tid + 256) >> 2, c1 = tid & 3;
    int t0 = s_tok[r0], t1 = s_tok[r1];
    uint32_t dA0 = tile_off(r0, c0), dA1 = tile_off(r1, c1);

#pragma unroll
    for (int pc = 0; pc < STAGES-1; pc++) {
        uint32_t st = sb + pc*ST_SIZE;
        int k0 = pc*BK;
        cpasync16(st + ST_AH + dA0, g_xh + (size_t)t0*IN_LEN + k0 + c0*8);
        cpasync16(st + ST_AH + dA1, g_xh + (size_t)t1*IN_LEN + k0 + c1*8);
        cpasync16(st + ST_AL + dA0, g_xl + (size_t)t0*IN_LEN + k0 + c0*8);
        cpasync16(st + ST_AL + dA1, g_xl + (size_t)t1*IN_LEN + k0 + c1*8);
        cpasync16(st + ST_BH + dA0, whp + (size_t)r0*IN_LEN + k0 + c0*8);
        cpasync16(st + ST_BH + dA1, whp + (size_t)r1*IN_LEN + k0 + c1*8);
        cpasync16(st + ST_BL + dA0, wlp + (size_t)r0*IN_LEN + k0 + c0*8);
        cpasync16(st + ST_BL + dA1, wlp + (size_t)r1*IN_LEN + k0 + c1*8);
        cp_commit();
    }

    float acc[2][8][4];
#pragma unroll
    for (int mb = 0; mb < 2; mb++)
#pragma unroll
        for (int nb = 0; nb < 8; nb++)
#pragma unroll
            for (int j = 0; j < 4; j++) acc[mb][nb][j] = 0.f;

    int j4 = lane >> 3, l7 = lane & 7;

    for (int ch = 0; ch < NCH; ch++) {
        asm volatile("cp.async.wait_group %0;" :: "n"(STAGES-2));
        __syncthreads();
        int nf = ch + STAGES - 1;
        if (nf < NCH) {
            uint32_t st = sb + (nf % STAGES)*ST_SIZE;
            int k0 = nf*BK;
            cpasync16(st + ST_AH + dA0, g_xh + (size_t)t0*IN_LEN + k0 + c0*8);
            cpasync16(st + ST_AH + dA1, g_xh + (size_t)t1*IN_LEN + k0 + c1*8);
            cpasync16(st + ST_AL + dA0, g_xl + (size_t)t0*IN_LEN + k0 + c0*8);
            cpasync16(st + ST_AL + dA1, g_xl + (size_t)t1*IN_LEN + k0 + c1*8);
            cpasync16(st + ST_BH + dA0, whp + (size_t)r0*IN_LEN + k0 + c0*8);
            cpasync16(st + ST_BH + dA1, whp + (size_t)r1*IN_LEN + k0 + c1*8);
            cpasync16(st + ST_BL + dA0, wlp + (size_t)r0*IN_LEN + k0 + c0*8);
            cpasync16(st + ST_BL + dA1, wlp + (size_t)r1*IN_LEN + k0 + c1*8);
        }
        cp_commit();

        uint32_t st = sb + (ch % STAGES)*ST_SIZE;
#pragma unroll
        for (int k16 = 0; k16 < 2; k16++) {
            uint32_t ah[2][4], al[2][4];
#pragma unroll
            for (int mb = 0; mb < 2; mb++) {
                int row = wm*32 + mb*16 + ((j4 & 1) << 3) + l7;
                int c   = k16*2 + (j4 >> 1);
                uint32_t o = tile_off(row, c);
                ldsm4(ah[mb], st + ST_AH + o);
                ldsm4(al[mb], st + ST_AL + o);
            }
            // stream B per 16-row pair p (nb = 2p, 2p+1) to cut live registers
#pragma unroll
            for (int p = 0; p < 4; p++) {
                int row = wn*64 + p*16 + ((j4 >> 1) << 3) + l7;
                int c   = k16*2 + (j4 & 1);
                uint32_t o = tile_off(row, c);
                uint32_t bh[4], bl[4];
                ldsm4(bh, st + ST_BH + o);
                ldsm4(bl, st + ST_BL + o);
#pragma unroll
                for (int mb = 0; mb < 2; mb++)
#pragma unroll
                    for (int h = 0; h < 2; h++) {
                        float* a = acc[mb][2*p + h];
                        mma16816(a, ah[mb], &bh[h*2]);
                        mma16816(a, ah[mb], &bl[h*2]);
                        mma16816(a, al[mb], &bh[h*2]);
                    }
            }
        }
    }

    int rl_lo = wm*32 + (lane >> 2);
    int cc    = cbase + wn*64 + (lane & 3)*2;
#pragma unroll
    for (int mb = 0; mb < 2; mb++) {
#pragma unroll
        for (int half = 0; half < 2; half++) {
            int rl = rl_lo + mb*16 + half*8;
            if (rl < nrows) {
                float cf = s_coef[rl];
                float* dst = g_stage + (size_t)(rbase + rl)*OUT_LEN + cc;
#pragma unroll
                for (int nb = 0; nb < 8; nb++) {
                    float2 v = make_float2(cf*acc[mb][nb][half*2], cf*acc[mb][nb][half*2+1]);
                    *(float2*)(dst + nb*8) = v;
                }
            }
        }
    }
}

// ---------------- K7: compose ----------------
__global__ void k_final(float* __restrict__ out) {
    int t = blockIdx.x;
    int i = threadIdx.x;
    int e0 = g_sel[2*t], e1 = g_sel[2*t+1];
    float r0 = g_rw[2*t], r1 = g_rw[2*t+1];
    int s0 = g_tslot[2*t], s1 = g_tslot[2*t+1];
    float4 b0 = *(const float4*)(g_bet + e0*OUT_LEN + i*4);
    float4 b1 = *(const float4*)(g_bet + e1*OUT_LEN + i*4);
    float4 a0 = *(const float4*)(g_stage + (size_t)s0*OUT_LEN + i*4);
    float4 a1 = *(const float4*)(g_stage + (size_t)s1*OUT_LEN + i*4);
    float4 o;
    o.x = fmaf(r0, b0.x, fmaf(r1, b1.x, a0.x + a1.x));
    o.y = fmaf(r0, b0.y, fmaf(r1, b1.y, a0.y + a1.y));
    o.z = fmaf(r0, b0.z, fmaf(r1, b1.z, a0.z + a1.z));
    o.w = fmaf(r0, b0.w, fmaf(r1, b1.w, a0.w + a1.w));
    *(float4*)(out + (size_t)t*OUT_LEN + i*4) = o;
}

// ---------------- launch ----------------
extern "C" void kernel_launch(void* const* d_in, const int* in_sizes, int n_in,
                              void* d_out, int out_size) {
    const float* x      = (const float*)d_in[0];
    const float* ins    = (const float*)d_in[1];
    const float* gatew  = (const float*)d_in[2];
    const float* ew     = (const float*)d_in[3];
    const float* eb     = (const float*)d_in[4];
    const float* gammaw = (const float*)d_in[5];
    const float* betaw  = (const float*)d_in[6];
    const float* rmod   = (const float*)d_in[7];
    float* out = (float*)d_out;

    cudaFuncSetAttribute(k_gemm_tc, cudaFuncAttributeMaxDynamicSharedMemorySize, DYN_SMEM);

    k_convw  <<<dim3(NE, OUT_LEN/32, IN_LEN/32), 256>>>(ew);
    k_prep   <<<1, 512>>>(ins, rmod, gammaw);
    k_beta   <<<dim3(NE, OUT_LEN/128), 512>>>(betaw, eb);
    k_route  <<<N_TOK/32, 256>>>(x, gatew);
    k_scatter<<<N_TOK/256, 256>>>();
    k_gemm_tc<<<dim3(MAX_TILES, OUT_LEN/128), 256, DYN_SMEM>>>();
    k_final  <<<N_TOK, 128>>>(out);
}

// round 6
// speedup vs baseline: 2.2574x; 1.1696x over previous
#include <cuda_runtime.h>
#include <cuda_fp16.h>
#include <math.h>
#include <stdint.h>

#define N_TOK   8192
#define IN_LEN  512
#define OUT_LEN 512
#define NE      8
#define NI      16
#define NPAIR   (N_TOK*2)
#define MAX_TILES (NPAIR/128 + NE)   // 136

// ---------------- device scratch ----------------
__device__ float g_mean_ins[OUT_LEN];
__device__ float g_rgamma[NE];
__device__ float g_gam[NE];
__device__ float g_bet[NE*OUT_LEN];
__device__ int   g_sel[NPAIR];
__device__ float g_rw[NPAIR];
__device__ int   g_count[NE];
__device__ int   g_cursor[NE];
__device__ int   g_list[NPAIR];
__device__ float g_lcoef[NPAIR];
__device__ int   g_tslot[NPAIR];
__device__ float g_stage[(size_t)NPAIR*OUT_LEN];
__device__ __half g_wh[(size_t)NE*OUT_LEN*IN_LEN];   // w rounded to fp16, [E,N,K]
__device__ __half g_xh[(size_t)N_TOK*IN_LEN];        // x hi fp16
__device__ __half g_xl[(size_t)N_TOK*IN_LEN];        // x lo fp16 (residual)

// ---------------- PTX helpers (sm_80-generic; ptxas targets plain sm_103) ----------
__device__ __forceinline__ uint32_t smem_u32(const void* p) {
    uint32_t a;
    asm("{ .reg .u64 t; cvta.to.shared.u64 t, %1; cvt.u32.u64 %0, t; }" : "=r"(a) : "l"(p));
    return a;
}
__device__ __forceinline__ void cpasync16(uint32_t dst, const void* src) {
    asm volatile("cp.async.cg.shared.global [%0], [%1], 16;" :: "r"(dst), "l"(src));
}
__device__ __forceinline__ void cp_commit() { asm volatile("cp.async.commit_group;" ::: "memory"); }
__device__ __forceinline__ void ldsm4(uint32_t* r, uint32_t addr) {
    asm volatile("ldmatrix.sync.aligned.m8n8.x4.shared.b16 {%0,%1,%2,%3}, [%4];"
                 : "=r"(r[0]), "=r"(r[1]), "=r"(r[2]), "=r"(r[3]) : "r"(addr));
}
__device__ __forceinline__ void mma16816(float* d, const uint32_t* a, const uint32_t* b) {
    asm volatile(
        "mma.sync.aligned.m16n8k16.row.col.f32.f16.f16.f32 "
        "{%0,%1,%2,%3}, {%4,%5,%6,%7}, {%8,%9}, {%0,%1,%2,%3};"
        : "+f"(d[0]), "+f"(d[1]), "+f"(d[2]), "+f"(d[3])
        : "r"(a[0]), "r"(a[1]), "r"(a[2]), "r"(a[3]), "r"(b[0]), "r"(b[1]));
}
__device__ __forceinline__ uint32_t pkhf(float a, float b) {
    __half2 h = __floats2half2_rn(a, b);
    return *(uint32_t*)&h;
}

// ---------------- K1: mean_ins, rgamma, gam; zero counters ----------------
__global__ void k_prep(const float* __restrict__ ins,
                       const float* __restrict__ rmod,
                       const float* __restrict__ gammaw) {
    int h = threadIdx.x;
    float s = 0.f;
#pragma unroll
    for (int n = 0; n < NI; n++) s += ins[n*OUT_LEN + h];
    s *= (1.f/NI);
    g_mean_ins[h] = s;
    __shared__ float sm[OUT_LEN];
    sm[h] = s;
    if (h < NE) { g_count[h] = 0; g_cursor[h] = 0; }
    __syncthreads();
    if (h < NE) {
        float a = 0.f, b = 0.f;
        for (int k = 0; k < OUT_LEN; k++) {
            float m = sm[k];
            a += m * rmod[k*NE + h];
            b += m * gammaw[h*OUT_LEN + k];
        }
        g_rgamma[h] = a;
        g_gam[h]    = b;
    }
}

// ---------------- K2: bet_eff ----------------
__global__ __launch_bounds__(512) void k_beta(const float* __restrict__ betaw,
                                              const float* __restrict__ eb) {
    int e  = blockIdx.x;
    int d  = blockIdx.y*128 + (threadIdx.x & 127);
    int hg = threadIdx.x >> 7;
    const float* bw = betaw + (size_t)e*OUT_LEN*OUT_LEN + d;
    float s = 0.f;
#pragma unroll 8
    for (int h = hg*128; h < hg*128 + 128; h++)
        s += g_mean_ins[h] * bw[(size_t)h*OUT_LEN];
    __shared__ float red[512];
    red[threadIdx.x] = s;
    __syncthreads();
    if (hg == 0) {
        float tot = red[threadIdx.x] + red[threadIdx.x+128]
                  + red[threadIdx.x+256] + red[threadIdx.x+384];
        g_bet[e*OUT_LEN + d] = tot + g_gam[e] * eb[e*OUT_LEN + d];
    }
}

// ---------------- K_convw: expert_w [E,K,N] -> fp16 [E,N,K] ----------------
__global__ __launch_bounds__(256) void k_convw(const float* __restrict__ ew) {
    __shared__ float t[32][33];
    int e = blockIdx.x, nb = blockIdx.y*32, kb = blockIdx.z*32;
    int tx = threadIdx.x & 31, ty = threadIdx.x >> 5;
    const float* src = ew + ((size_t)e*IN_LEN + kb)*OUT_LEN + nb;
#pragma unroll
    for (int i = ty; i < 32; i += 8)
        t[i][tx] = src[(size_t)i*OUT_LEN + tx];
    __syncthreads();
    int r  = threadIdx.x >> 3;
    int kq = threadIdx.x & 7;
    uint2 hp = make_uint2(pkhf(t[kq*4+0][r], t[kq*4+1][r]),
                          pkhf(t[kq*4+2][r], t[kq*4+3][r]));
    size_t o = ((size_t)e*OUT_LEN + nb + r)*IN_LEN + kb + kq*4;
    *(uint2*)(g_wh + o) = hp;
}

// ---------------- K3: routing + x fp16 split; 1 token/warp, grid 1024 -----------
__global__ __launch_bounds__(256, 4) void k_route(const float* __restrict__ x,
                                                  const float* __restrict__ gatew) {
    __shared__ float sgw[NE][IN_LEN];   // 16 KB, transposed
    int tid = threadIdx.x;
    for (int i = tid; i < IN_LEN*NE; i += 256)
        sgw[i & 7][i >> 3] = gatew[i];
    __syncthreads();
    int lane = tid & 31, wid = tid >> 5;
    int t = blockIdx.x*8 + wid;
    const float4* xr = (const float4*)(x + (size_t)t*IN_LEN);
    float acc[NE];
#pragma unroll
    for (int e = 0; e < NE; e++) acc[e] = 0.f;
#pragma unroll
    for (int j = 0; j < 4; j++) {
        float4 v = xr[j*32 + lane];
        __half h0 = __float2half_rn(v.x), h1 = __float2half_rn(v.y);
        __half h2 = __float2half_rn(v.z), h3 = __float2half_rn(v.w);
        uint2 hp;
        hp.x = (uint32_t)__half_as_ushort(h0) | ((uint32_t)__half_as_ushort(h1) << 16);
        hp.y = (uint32_t)__half_as_ushort(h2) | ((uint32_t)__half_as_ushort(h3) << 16);
        uint2 lp = make_uint2(
            pkhf(v.x - __half2float(h0), v.y - __half2float(h1)),
            pkhf(v.z - __half2float(h2), v.w - __half2float(h3)));
        size_t xo = (size_t)t*IN_LEN + j*128 + lane*4;
        *(uint2*)(g_xh + xo) = hp;
        *(uint2*)(g_xl + xo) = lp;
#pragma unroll
        for (int e = 0; e < NE; e++) {
            float4 g = *(const float4*)&sgw[e][j*128 + lane*4];
            acc[e] += v.x*g.x + v.y*g.y + v.z*g.z + v.w*g.w;
        }
    }
#pragma unroll
    for (int e = 0; e < NE; e++)
#pragma unroll
        for (int o = 16; o > 0; o >>= 1)
            acc[e] += __shfl_xor_sync(0xffffffffu, acc[e], o);
    if (lane == 0) {
        float l[NE];
#pragma unroll
        for (int e = 0; e < NE; e++) l[e] = acc[e] + g_rgamma[e];
        float m = l[0];
#pragma unroll
        for (int e = 1; e < NE; e++) m = fmaxf(m, l[e]);
        float s = 0.f;
#pragma unroll
        for (int e = 0; e < NE; e++) s += expf(l[e] - m);
        float inv = 1.f / s;
        int e0 = 0; float v0 = l[0];
#pragma unroll
        for (int e = 1; e < NE; e++) if (l[e] > v0) { v0 = l[e]; e0 = e; }
        int e1 = -1; float v1 = -INFINITY;
#pragma unroll
        for (int e = 0; e < NE; e++) if (e != e0 && l[e] > v1) { v1 = l[e]; e1 = e; }
        g_sel[2*t]   = e0;  g_sel[2*t+1] = e1;
        g_rw[2*t]    = expf(v0 - m) * inv;
        g_rw[2*t+1]  = expf(v1 - m) * inv;
        atomicAdd(&g_count[e0], 1);
        atomicAdd(&g_count[e1], 1);
    }
}

// ---------------- K5: scatter ----------------
__global__ void k_scatter() {
    __shared__ int soff[NE];
    if (threadIdx.x < NE) {
        int off = 0;
        for (int i = 0; i < (int)threadIdx.x; i++) off += g_count[i];
        soff[threadIdx.x] = off;
    }
    __syncthreads();
    int t = blockIdx.x*blockDim.x + threadIdx.x;
    if (t >= N_TOK) return;
#pragma unroll
    for (int k = 0; k < 2; k++) {
        int e = g_sel[2*t + k];
        float rw = g_rw[2*t + k];
        int slot = soff[e] + atomicAdd(&g_cursor[e], 1);
        g_list[slot]  = t;
        g_lcoef[slot] = rw * g_gam[e];
        g_tslot[2*t + k] = slot;
    }
}

// ---------------- K6: HMMA grouped GEMM 128x128, BK=32, fp16 2-split, 4-stage ----
#define BK        32
#define NCH       (IN_LEN/BK)      // 16
#define STAGES    4
#define ST_AH     0
#define ST_AL     8192
#define ST_B      16384
#define ST_SIZE   24576
#define OFF_TOK   (STAGES*ST_SIZE)            // 98304
#define OFF_COEF  (OFF_TOK + 512)
#define DYN_SMEM  (OFF_COEF + 512)            // 99328

__device__ __forceinline__ uint32_t tile_off(int row, int c) {
    return (uint32_t)(row*64 + ((c ^ ((row >> 1) & 3)) << 4));
}

__global__ __launch_bounds__(256, 2) void k_gemm_tc(void) {
    extern __shared__ char smem[];
    int rt = blockIdx.x;
    int e = -1, rbase = 0, nrows = 0;
    {
        int ts = 0, off = 0;
#pragma unroll
        for (int i = 0; i < NE; i++) {
            int cnt = g_count[i];
            int ti = (cnt + 127) >> 7;
            if (e < 0 && rt < ts + ti) {
                int tie = rt - ts;
                e = i; rbase = off + tie*128; nrows = cnt - tie*128;
            }
            ts += ti; off += cnt;
        }
    }
    if (e < 0) return;
    if (nrows > 128) nrows = 128;
    int cbase = blockIdx.y*128;

    uint32_t sb = smem_u32(smem);
    int tid = threadIdx.x;
    int lane = tid & 31;
    int wid = tid >> 5;
    int wm = wid >> 1;
    int wn = wid & 1;

    int*   s_tok  = (int*)(smem + OFF_TOK);
    float* s_coef = (float*)(smem + OFF_COEF);
    if (tid < 128) {
        s_tok[tid]  = (tid < nrows) ? g_list[rbase + tid]  : g_list[rbase];
        s_coef[tid] = (tid < nrows) ? g_lcoef[rbase + tid] : 0.f;
    }
    __syncthreads();

    const __half* whp = g_wh + ((size_t)e*OUT_LEN + cbase)*IN_LEN;

    int r0 = tid >> 2,         c0 = tid & 3;
    int r1 = (tid + 256) >> 2, c1 = tid & 3;
    int t0 = s_tok[r0], t1 = s_tok[r1];
    uint32_t dA0 = tile_off(r0, c0), dA1 = tile_off(r1, c1);

#pragma unroll
    for (int pc = 0; pc < STAGES-1; pc++) {
        uint32_t st = sb + pc*ST_SIZE;
        int k0 = pc*BK;
        cpasync16(st + ST_AH + dA0, g_xh + (size_t)t0*IN_LEN + k0 + c0*8);
        cpasync16(st + ST_AH + dA1, g_xh + (size_t)t1*IN_LEN + k0 + c1*8);
        cpasync16(st + ST_AL + dA0, g_xl + (size_t)t0*IN_LEN + k0 + c0*8);
        cpasync16(st + ST_AL + dA1, g_xl + (size_t)t1*IN_LEN + k0 + c1*8);
        cpasync16(st + ST_B  + dA0, whp + (size_t)r0*IN_LEN + k0 + c0*8);
        cpasync16(st + ST_B  + dA1, whp + (size_t)r1*IN_LEN + k0 + c1*8);
        cp_commit();
    }

    float acc[2][8][4];
#pragma unroll
    for (int mb = 0; mb < 2; mb++)
#pragma unroll
        for (int nb = 0; nb < 8; nb++)
#pragma unroll
            for (int j = 0; j < 4; j++) acc[mb][nb][j] = 0.f;

    int j4 = lane >> 3, l7 = lane & 7;

    for (int ch = 0; ch < NCH; ch++) {
        asm volatile("cp.async.wait_group %0;" :: "n"(STAGES-2));
        __syncthreads();
        int nf = ch + STAGES - 1;
        if (nf < NCH) {
            uint32_t st = sb + (nf % STAGES)*ST_SIZE;
            int k0 = nf*BK;
            cpasync16(st + ST_AH + dA0, g_xh + (size_t)t0*IN_LEN + k0 + c0*8);
            cpasync16(st + ST_AH + dA1, g_xh + (size_t)t1*IN_LEN + k0 + c1*8);
            cpasync16(st + ST_AL + dA0, g_xl + (size_t)t0*IN_LEN + k0 + c0*8);
            cpasync16(st + ST_AL + dA1, g_xl + (size_t)t1*IN_LEN + k0 + c1*8);
            cpasync16(st + ST_B  + dA0, whp + (size_t)r0*IN_LEN + k0 + c0*8);
            cpasync16(st + ST_B  + dA1, whp + (size_t)r1*IN_LEN + k0 + c1*8);
        }
        cp_commit();

        uint32_t st = sb + (ch % STAGES)*ST_SIZE;
#pragma unroll
        for (int k16 = 0; k16 < 2; k16++) {
            uint32_t ah[2][4], al[2][4];
#pragma unroll
            for (int mb = 0; mb < 2; mb++) {
                int row = wm*32 + mb*16 + ((j4 & 1) << 3) + l7;
                int c   = k16*2 + (j4 >> 1);
                uint32_t o = tile_off(row, c);
                ldsm4(ah[mb], st + ST_AH + o);
                ldsm4(al[mb], st + ST_AL + o);
            }
#pragma unroll
            for (int p = 0; p < 4; p++) {
                int row = wn*64 + p*16 + ((j4 >> 1) << 3) + l7;
                int c   = k16*2 + (j4 & 1);
                uint32_t o = tile_off(row, c);
                uint32_t bh[4];
                ldsm4(bh, st + ST_B + o);
#pragma unroll
                for (int mb = 0; mb < 2; mb++)
#pragma unroll
                    for (int h = 0; h < 2; h++) {
                        float* a = acc[mb][2*p + h];
                        mma16816(a, ah[mb], &bh[h*2]);
                        mma16816(a, al[mb], &bh[h*2]);
                    }
            }
        }
    }

    int rl_lo = wm*32 + (lane >> 2);
    int cc    = cbase + wn*64 + (lane & 3)*2;
#pragma unroll
    for (int mb = 0; mb < 2; mb++) {
#pragma unroll
        for (int half = 0; half < 2; half++) {
            int rl = rl_lo + mb*16 + half*8;
            if (rl < nrows) {
                float cf = s_coef[rl];
                float* dst = g_stage + (size_t)(rbase + rl)*OUT_LEN + cc;
#pragma unroll
                for (int nb = 0; nb < 8; nb++) {
                    float2 v = make_float2(cf*acc[mb][nb][half*2], cf*acc[mb][nb][half*2+1]);
                    *(float2*)(dst + nb*8) = v;
                }
            }
        }
    }
}

// ---------------- K7: compose ----------------
__global__ void k_final(float* __restrict__ out) {
    int t = blockIdx.x;
    int i = threadIdx.x;
    int e0 = g_sel[2*t], e1 = g_sel[2*t+1];
    float r0 = g_rw[2*t], r1 = g_rw[2*t+1];
    int s0 = g_tslot[2*t], s1 = g_tslot[2*t+1];
    float4 b0 = *(const float4*)(g_bet + e0*OUT_LEN + i*4);
    float4 b1 = *(const float4*)(g_bet + e1*OUT_LEN + i*4);
    float4 a0 = *(const float4*)(g_stage + (size_t)s0*OUT_LEN + i*4);
    float4 a1 = *(const float4*)(g_stage + (size_t)s1*OUT_LEN + i*4);
    float4 o;
    o.x = fmaf(r0, b0.x, fmaf(r1, b1.x, a0.x + a1.x));
    o.y = fmaf(r0, b0.y, fmaf(r1, b1.y, a0.y + a1.y));
    o.z = fmaf(r0, b0.z, fmaf(r1, b1.z, a0.z + a1.z));
    o.w = fmaf(r0, b0.w, fmaf(r1, b1.w, a0.w + a1.w));
    *(float4*)(out + (size_t)t*OUT_LEN + i*4) = o;
}

// ---------------- launch ----------------
extern "C" void kernel_launch(void* const* d_in, const int* in_sizes, int n_in,
                              void* d_out, int out_size) {
    const float* x      = (const float*)d_in[0];
    const float* ins    = (const float*)d_in[1];
    const float* gatew  = (const float*)d_in[2];
    const float* ew     = (const float*)d_in[3];
    const float* eb     = (const float*)d_in[4];
    const float* gammaw = (const float*)d_in[5];
    const float* betaw  = (const float*)d_in[6];
    const float* rmod   = (const float*)d_in[7];
    float* out = (float*)d_out;

    cudaFuncSetAttribute(k_gemm_tc, cudaFuncAttributeMaxDynamicSharedMemorySize, DYN_SMEM);

    k_convw  <<<dim3(NE, OUT_LEN/32, IN_LEN/32), 256>>>(ew);
    k_prep   <<<1, 512>>>(ins, rmod, gammaw);
    k_beta   <<<dim3(NE, OUT_LEN/128), 512>>>(betaw, eb);
    k_route  <<<N_TOK/8, 256>>>(x, gatew);
    k_scatter<<<N_TOK/256, 256>>>();
    k_gemm_tc<<<dim3(MAX_TILES, OUT_LEN/128), 256, DYN_SMEM>>>();
    k_final  <<<N_TOK, 128>>>(out);
}

// round 7
// speedup vs baseline: 2.3508x; 1.0414x over previous
#include <cuda_runtime.h>
#include <cuda_fp16.h>
#include <math.h>
#include <stdint.h>

#define N_TOK   8192
#define IN_LEN  512
#define OUT_LEN 512
#define NE      8
#define NI      16
#define NPAIR   (N_TOK*2)
#define MAX_TILES (NPAIR/128 + NE)   // 136

// ---------------- device scratch ----------------
__device__ float g_mean_ins[OUT_LEN];
__device__ float g_rgamma[NE];
__device__ float g_gam[NE];
__device__ float g_bet[NE*OUT_LEN];
__device__ int   g_sel[NPAIR];
__device__ float g_rw[NPAIR];
__device__ int   g_count[NE];
__device__ int   g_cursor[NE];
__device__ int   g_list[NPAIR];
__device__ float g_lcoef[NPAIR];
__device__ int   g_tslot[NPAIR];
__device__ __half g_stage[(size_t)NPAIR*OUT_LEN];    // fp16 staging (was fp32)
__device__ __half g_wh[(size_t)NE*OUT_LEN*IN_LEN];   // w fp16, [E,N,K]
__device__ __half g_xh[(size_t)N_TOK*IN_LEN];        // x hi fp16
__device__ __half g_xl[(size_t)N_TOK*IN_LEN];        // x lo fp16 (residual)

// ---------------- PTX helpers ----------------
__device__ __forceinline__ uint32_t smem_u32(const void* p) {
    uint32_t a;
    asm("{ .reg .u64 t; cvta.to.shared.u64 t, %1; cvt.u32.u64 %0, t; }" : "=r"(a) : "l"(p));
    return a;
}
__device__ __forceinline__ void cpasync16(uint32_t dst, const void* src) {
    asm volatile("cp.async.cg.shared.global [%0], [%1], 16;" :: "r"(dst), "l"(src));
}
__device__ __forceinline__ void cp_commit() { asm volatile("cp.async.commit_group;" ::: "memory"); }
__device__ __forceinline__ void ldsm4(uint32_t* r, uint32_t addr) {
    asm volatile("ldmatrix.sync.aligned.m8n8.x4.shared.b16 {%0,%1,%2,%3}, [%4];"
                 : "=r"(r[0]), "=r"(r[1]), "=r"(r[2]), "=r"(r[3]) : "r"(addr));
}
__device__ __forceinline__ void mma16816(float* d, const uint32_t* a, const uint32_t* b) {
    asm volatile(
        "mma.sync.aligned.m16n8k16.row.col.f32.f16.f16.f32 "
        "{%0,%1,%2,%3}, {%4,%5,%6,%7}, {%8,%9}, {%0,%1,%2,%3};"
        : "+f"(d[0]), "+f"(d[1]), "+f"(d[2]), "+f"(d[3])
        : "r"(a[0]), "r"(a[1]), "r"(a[2]), "r"(a[3]), "r"(b[0]), "r"(b[1]));
}
__device__ __forceinline__ uint32_t pkhf(float a, float b) {
    __half2 h = __floats2half2_rn(a, b);
    return *(uint32_t*)&h;
}

// ---------------- K1 ----------------
__global__ void k_prep(const float* __restrict__ ins,
                       const float* __restrict__ rmod,
                       const float* __restrict__ gammaw) {
    int h = threadIdx.x;
    float s = 0.f;
#pragma unroll
    for (int n = 0; n < NI; n++) s += ins[n*OUT_LEN + h];
    s *= (1.f/NI);
    g_mean_ins[h] = s;
    __shared__ float sm[OUT_LEN];
    sm[h] = s;
    if (h < NE) { g_count[h] = 0; g_cursor[h] = 0; }
    __syncthreads();
    if (h < NE) {
        float a = 0.f, b = 0.f;
        for (int k = 0; k < OUT_LEN; k++) {
            float m = sm[k];
            a += m * rmod[k*NE + h];
            b += m * gammaw[h*OUT_LEN + k];
        }
        g_rgamma[h] = a;
        g_gam[h]    = b;
    }
}

// ---------------- K2 ----------------
__global__ __launch_bounds__(512) void k_beta(const float* __restrict__ betaw,
                                              const float* __restrict__ eb) {
    int e  = blockIdx.x;
    int d  = blockIdx.y*128 + (threadIdx.x & 127);
    int hg = threadIdx.x >> 7;
    const float* bw = betaw + (size_t)e*OUT_LEN*OUT_LEN + d;
    float s = 0.f;
#pragma unroll 8
    for (int h = hg*128; h < hg*128 + 128; h++)
        s += g_mean_ins[h] * bw[(size_t)h*OUT_LEN];
    __shared__ float red[512];
    red[threadIdx.x] = s;
    __syncthreads();
    if (hg == 0) {
        float tot = red[threadIdx.x] + red[threadIdx.x+128]
                  + red[threadIdx.x+256] + red[threadIdx.x+384];
        g_bet[e*OUT_LEN + d] = tot + g_gam[e] * eb[e*OUT_LEN + d];
    }
}

// ---------------- K_convw ----------------
__global__ __launch_bounds__(256) void k_convw(const float* __restrict__ ew) {
    __shared__ float t[32][33];
    int e = blockIdx.x, nb = blockIdx.y*32, kb = blockIdx.z*32;
    int tx = threadIdx.x & 31, ty = threadIdx.x >> 5;
    const float* src = ew + ((size_t)e*IN_LEN + kb)*OUT_LEN + nb;
#pragma unroll
    for (int i = ty; i < 32; i += 8)
        t[i][tx] = src[(size_t)i*OUT_LEN + tx];
    __syncthreads();
    int r  = threadIdx.x >> 3;
    int kq = threadIdx.x & 7;
    uint2 hp = make_uint2(pkhf(t[kq*4+0][r], t[kq*4+1][r]),
                          pkhf(t[kq*4+2][r], t[kq*4+3][r]));
    size_t o = ((size_t)e*OUT_LEN + nb + r)*IN_LEN + kb + kq*4;
    *(uint2*)(g_wh + o) = hp;
}

// ---------------- K3: routing + x split; loads hoisted for MLP=4 ----------------
__global__ __launch_bounds__(256, 3) void k_route(const float* __restrict__ x,
                                                  const float* __restrict__ gatew) {
    __shared__ float sgw[NE][IN_LEN];
    int tid = threadIdx.x;
    for (int i = tid; i < IN_LEN*NE; i += 256)
        sgw[i & 7][i >> 3] = gatew[i];
    __syncthreads();
    int lane = tid & 31, wid = tid >> 5;
    int t = blockIdx.x*8 + wid;
    const float4* xr = (const float4*)(x + (size_t)t*IN_LEN);

    // all 4 global loads in flight before any use
    float4 v[4];
#pragma unroll
    for (int j = 0; j < 4; j++) v[j] = xr[j*32 + lane];

    float acc[NE];
#pragma unroll
    for (int e = 0; e < NE; e++) acc[e] = 0.f;
#pragma unroll
    for (int j = 0; j < 4; j++) {
        __half h0 = __float2half_rn(v[j].x), h1 = __float2half_rn(v[j].y);
        __half h2 = __float2half_rn(v[j].z), h3 = __float2half_rn(v[j].w);
        uint2 hp;
        hp.x = (uint32_t)__half_as_ushort(h0) | ((uint32_t)__half_as_ushort(h1) << 16);
        hp.y = (uint32_t)__half_as_ushort(h2) | ((uint32_t)__half_as_ushort(h3) << 16);
        uint2 lp = make_uint2(
            pkhf(v[j].x - __half2float(h0), v[j].y - __half2float(h1)),
            pkhf(v[j].z - __half2float(h2), v[j].w - __half2float(h3)));
        size_t xo = (size_t)t*IN_LEN + j*128 + lane*4;
        *(uint2*)(g_xh + xo) = hp;
        *(uint2*)(g_xl + xo) = lp;
#pragma unroll
        for (int e = 0; e < NE; e++) {
            float4 g = *(const float4*)&sgw[e][j*128 + lane*4];
            acc[e] += v[j].x*g.x + v[j].y*g.y + v[j].z*g.z + v[j].w*g.w;
        }
    }
#pragma unroll
    for (int e = 0; e < NE; e++)
#pragma unroll
        for (int o = 16; o > 0; o >>= 1)
            acc[e] += __shfl_xor_sync(0xffffffffu, acc[e], o);
    if (lane == 0) {
        float l[NE];
#pragma unroll
        for (int e = 0; e < NE; e++) l[e] = acc[e] + g_rgamma[e];
        float m = l[0];
#pragma unroll
        for (int e = 1; e < NE; e++) m = fmaxf(m, l[e]);
        float s = 0.f;
#pragma unroll
        for (int e = 0; e < NE; e++) s += expf(l[e] - m);
        float inv = 1.f / s;
        int e0 = 0; float v0 = l[0];
#pragma unroll
        for (int e = 1; e < NE; e++) if (l[e] > v0) { v0 = l[e]; e0 = e; }
        int e1 = -1; float v1 = -INFINITY;
#pragma unroll
        for (int e = 0; e < NE; e++) if (e != e0 && l[e] > v1) { v1 = l[e]; e1 = e; }
        g_sel[2*t]   = e0;  g_sel[2*t+1] = e1;
        g_rw[2*t]    = expf(v0 - m) * inv;
        g_rw[2*t+1]  = expf(v1 - m) * inv;
        atomicAdd(&g_count[e0], 1);
        atomicAdd(&g_count[e1], 1);
    }
}

// ---------------- K5: scatter ----------------
__global__ void k_scatter() {
    __shared__ int soff[NE];
    if (threadIdx.x < NE) {
        int off = 0;
        for (int i = 0; i < (int)threadIdx.x; i++) off += g_count[i];
        soff[threadIdx.x] = off;
    }
    __syncthreads();
    int t = blockIdx.x*blockDim.x + threadIdx.x;
    if (t >= N_TOK) return;
#pragma unroll
    for (int k = 0; k < 2; k++) {
        int e = g_sel[2*t + k];
        float rw = g_rw[2*t + k];
        int slot = soff[e] + atomicAdd(&g_cursor[e], 1);
        g_list[slot]  = t;
        g_lcoef[slot] = rw * g_gam[e];
        g_tslot[2*t + k] = slot;
    }
}

// ---------------- K6: HMMA GEMM 128x128, fp16 2-split, 4-stage, 2 y-passes -------
#define BK        32
#define NCH       (IN_LEN/BK)      // 16
#define STAGES    4
#define ST_AH     0
#define ST_AL     8192
#define ST_B      16384
#define ST_SIZE   24576
#define OFF_TOK   (STAGES*ST_SIZE)            // 98304
#define OFF_COEF  (OFF_TOK + 512)
#define DYN_SMEM  (OFF_COEF + 512)            // 99328

__device__ __forceinline__ uint32_t tile_off(int row, int c) {
    return (uint32_t)(row*64 + ((c ^ ((row >> 1) & 3)) << 4));
}

__global__ __launch_bounds__(256, 2) void k_gemm_tc(void) {
    extern __shared__ char smem[];
    int rt = blockIdx.x;
    int e = -1, rbase = 0, nrows = 0;
    {
        int ts = 0, off = 0;
#pragma unroll
        for (int i = 0; i < NE; i++) {
            int cnt = g_count[i];
            int ti = (cnt + 127) >> 7;
            if (e < 0 && rt < ts + ti) {
                int tie = rt - ts;
                e = i; rbase = off + tie*128; nrows = cnt - tie*128;
            }
            ts += ti; off += cnt;
        }
    }
    if (e < 0) return;
    if (nrows > 128) nrows = 128;

    uint32_t sb = smem_u32(smem);
    int tid = threadIdx.x;
    int lane = tid & 31;
    int wid = tid >> 5;
    int wm = wid >> 1;
    int wn = wid & 1;

    int*   s_tok  = (int*)(smem + OFF_TOK);
    float* s_coef = (float*)(smem + OFF_COEF);
    if (tid < 128) {
        s_tok[tid]  = (tid < nrows) ? g_list[rbase + tid]  : g_list[rbase];
        s_coef[tid] = (tid < nrows) ? g_lcoef[rbase + tid] : 0.f;
    }
    __syncthreads();

    int r0 = tid >> 2,         c0 = tid & 3;
    int r1 = (tid + 256) >> 2, c1 = tid & 3;
    int t0 = s_tok[r0], t1 = s_tok[r1];
    uint32_t dA0 = tile_off(r0, c0), dA1 = tile_off(r1, c1);
    int j4 = lane >> 3, l7 = lane & 7;

    for (int yp = 0; yp < 2; yp++) {
        int cbase = (blockIdx.y*2 + yp)*128;
        const __half* whp = g_wh + ((size_t)e*OUT_LEN + cbase)*IN_LEN;
        if (yp) __syncthreads();   // all warps done reading pass-0 smem

#pragma unroll
        for (int pc = 0; pc < STAGES-1; pc++) {
            uint32_t st = sb + pc*ST_SIZE;
            int k0 = pc*BK;
            cpasync16(st + ST_AH + dA0, g_xh + (size_t)t0*IN_LEN + k0 + c0*8);
            cpasync16(st + ST_AH + dA1, g_xh + (size_t)t1*IN_LEN + k0 + c1*8);
            cpasync16(st + ST_AL + dA0, g_xl + (size_t)t0*IN_LEN + k0 + c0*8);
            cpasync16(st + ST_AL + dA1, g_xl + (size_t)t1*IN_LEN + k0 + c1*8);
            cpasync16(st + ST_B  + dA0, whp + (size_t)r0*IN_LEN + k0 + c0*8);
            cpasync16(st + ST_B  + dA1, whp + (size_t)r1*IN_LEN + k0 + c1*8);
            cp_commit();
        }

        float acc[2][8][4];
#pragma unroll
        for (int mb = 0; mb < 2; mb++)
#pragma unroll
            for (int nb = 0; nb < 8; nb++)
#pragma unroll
                for (int j = 0; j < 4; j++) acc[mb][nb][j] = 0.f;

        for (int ch = 0; ch < NCH; ch++) {
            asm volatile("cp.async.wait_group %0;" :: "n"(STAGES-2));
            __syncthreads();
            int nf = ch + STAGES - 1;
            if (nf < NCH) {
                uint32_t st = sb + (nf % STAGES)*ST_SIZE;
                int k0 = nf*BK;
                cpasync16(st + ST_AH + dA0, g_xh + (size_t)t0*IN_LEN + k0 + c0*8);
                cpasync16(st + ST_AH + dA1, g_xh + (size_t)t1*IN_LEN + k0 + c1*8);
                cpasync16(st + ST_AL + dA0, g_xl + (size_t)t0*IN_LEN + k0 + c0*8);
                cpasync16(st + ST_AL + dA1, g_xl + (size_t)t1*IN_LEN + k0 + c1*8);
                cpasync16(st + ST_B  + dA0, whp + (size_t)r0*IN_LEN + k0 + c0*8);
                cpasync16(st + ST_B  + dA1, whp + (size_t)r1*IN_LEN + k0 + c1*8);
            }
            cp_commit();

            uint32_t st = sb + (ch % STAGES)*ST_SIZE;
#pragma unroll
            for (int k16 = 0; k16 < 2; k16++) {
                uint32_t ah[2][4], al[2][4];
#pragma unroll
                for (int mb = 0; mb < 2; mb++) {
                    int row = wm*32 + mb*16 + ((j4 & 1) << 3) + l7;
                    int c   = k16*2 + (j4 >> 1);
                    uint32_t o = tile_off(row, c);
                    ldsm4(ah[mb], st + ST_AH + o);
                    ldsm4(al[mb], st + ST_AL + o);
                }
#pragma unroll
                for (int p = 0; p < 4; p++) {
                    int row = wn*64 + p*16 + ((j4 >> 1) << 3) + l7;
                    int c   = k16*2 + (j4 & 1);
                    uint32_t o = tile_off(row, c);
                    uint32_t bh[4];
                    ldsm4(bh, st + ST_B + o);
#pragma unroll
                    for (int mb = 0; mb < 2; mb++)
#pragma unroll
                        for (int h = 0; h < 2; h++) {
                            float* a = acc[mb][2*p + h];
                            mma16816(a, ah[mb], &bh[h*2]);
                            mma16816(a, al[mb], &bh[h*2]);
                        }
                }
            }
        }

        // epilogue: scale by rw*gam, store fp16 pairs to staging
        int rl_lo = wm*32 + (lane >> 2);
        int cc    = cbase + wn*64 + (lane & 3)*2;
#pragma unroll
        for (int mb = 0; mb < 2; mb++) {
#pragma unroll
            for (int half = 0; half < 2; half++) {
                int rl = rl_lo + mb*16 + half*8;
                if (rl < nrows) {
                    float cf = s_coef[rl];
                    __half* dst = g_stage + (size_t)(rbase + rl)*OUT_LEN + cc;
#pragma unroll
                    for (int nb = 0; nb < 8; nb++)
                        *(uint32_t*)(dst + nb*8) =
                            pkhf(cf*acc[mb][nb][half*2], cf*acc[mb][nb][half*2+1]);
                }
            }
        }
    }
}

// ---------------- K7: compose (fp16 stage reads) ----------------
__global__ void k_final(float* __restrict__ out) {
    int t = blockIdx.x;
    int i = threadIdx.x;
    int e0 = g_sel[2*t], e1 = g_sel[2*t+1];
    float r0 = g_rw[2*t], r1 = g_rw[2*t+1];
    int s0 = g_tslot[2*t], s1 = g_tslot[2*t+1];
    float4 b0 = *(const float4*)(g_bet + e0*OUT_LEN + i*4);
    float4 b1 = *(const float4*)(g_bet + e1*OUT_LEN + i*4);
    uint2 u0 = *(const uint2*)(g_stage + (size_t)s0*OUT_LEN + i*4);
    uint2 u1 = *(const uint2*)(g_stage + (size_t)s1*OUT_LEN + i*4);
    float2 a0 = __half22float2(*(__half2*)&u0.x);
    float2 a1 = __half22float2(*(__half2*)&u0.y);
    float2 c0 = __half22float2(*(__half2*)&u1.x);
    float2 c1 = __half22float2(*(__half2*)&u1.y);
    float4 o;
    o.x = fmaf(r0, b0.x, fmaf(r1, b1.x, a0.x + c0.x));
    o.y = fmaf(r0, b0.y, fmaf(r1, b1.y, a0.y + c0.y));
    o.z = fmaf(r0, b0.z, fmaf(r1, b1.z, a1.x + c1.x));
    o.w = fmaf(r0, b0.w, fmaf(r1, b1.w, a1.y + c1.y));
    *(float4*)(out + (size_t)t*OUT_LEN + i*4) = o;
}

// ---------------- launch ----------------
extern "C" void kernel_launch(void* const* d_in, const int* in_sizes, int n_in,
                              void* d_out, int out_size) {
    const float* x      = (const float*)d_in[0];
    const float* ins    = (const float*)d_in[1];
    const float* gatew  = (const float*)d_in[2];
    const float* ew     = (const float*)d_in[3];
    const float* eb     = (const float*)d_in[4];
    const float* gammaw = (const float*)d_in[5];
    const float* betaw  = (const float*)d_in[6];
    const float* rmod   = (const float*)d_in[7];
    float* out = (float*)d_out;

    cudaFuncSetAttribute(k_gemm_tc, cudaFuncAttributeMaxDynamicSharedMemorySize, DYN_SMEM);

    k_convw  <<<dim3(NE, OUT_LEN/32, IN_LEN/32), 256>>>(ew);
    k_prep   <<<1, 512>>>(ins, rmod, gammaw);
    k_beta   <<<dim3(NE, OUT_LEN/128), 512>>>(betaw, eb);
    k_route  <<<N_TOK/8, 256>>>(x, gatew);
    k_scatter<<<N_TOK/256, 256>>>();
    k_gemm_tc<<<dim3(MAX_TILES, 2), 256, DYN_SMEM>>>();
    k_final  <<<N_TOK, 128>>>(out);
}